// round 14
// baseline (speedup 1.0000x reference)
#include <cuda_runtime.h>
#include <cuda_fp16.h>
#include <math.h>
#include <stdint.h>

#define Bn   128
#define Kn   32
#define In   12000
#define Hn   600
#define LATn 200
#define ROWS (Bn*Kn)      // 4096
#define ENCn (2*LATn)     // 400

#define KPAD1 12096       // In padded to 96 (126 x 96-chunks)
#define NPAD1 640         // Hn padded to 160
#define KPAD2 224         // LATn padded (7 x 32-chunks)
#define NPAD2 12032       // In padded (47 x 256 n-tiles)
#define HPADK 608         // Hn padded to 32  (K of gemm2)
#define NPADW 512         // ENCn padded to 128 (N of gemm2)

#define Z_OFF  0
#define NO_OFF (ROWS*LATn)                 // 819200
#define KL_OFF (NO_OFF + Bn*In)            // 2355200
#define X_OFF  (KL_OFF + 1)                // 2355201

typedef __half HF;

// ---------------- scratch (no allocation allowed) ----------------
__device__ float  g_enc[ROWS*ENCn];
__device__ double g_klp[512];
__device__ HF g_xh [(size_t)ROWS*KPAD1];
__device__ HF g_w1h[(size_t)NPAD1*KPAD1];
__device__ HF g_hh [(size_t)ROWS*HPADK];
__device__ HF g_w2h[(size_t)NPADW*HPADK];
__device__ HF g_znh[(size_t)ROWS*KPAD2];
__device__ HF g_ith[(size_t)NPAD2*KPAD2];

// ==================== helpers ====================
__device__ __forceinline__ uint32_t smem_u32(const void* p) {
    uint32_t a;
    asm("{ .reg .u64 t; cvta.to.shared.u64 t, %1; cvt.u32.u64 %0, t; }" : "=r"(a) : "l"(p));
    return a;
}
#define CP16(dst, src) asm volatile("cp.async.cg.shared.global [%0], [%1], 16;" :: "r"(dst), "l"(src) : "memory")
#define CP_COMMIT()    asm volatile("cp.async.commit_group;" ::: "memory")
#define CP_WAIT1()     asm volatile("cp.async.wait_group 1;" ::: "memory")
#define CP_WAIT0()     asm volatile("cp.async.wait_group 0;" ::: "memory")

__device__ __forceinline__ void ldsm4(uint32_t r[4], uint32_t addr) {
    asm volatile("ldmatrix.sync.aligned.m8n8.x4.shared.b16 {%0,%1,%2,%3}, [%4];"
        : "=r"(r[0]), "=r"(r[1]), "=r"(r[2]), "=r"(r[3]) : "r"(addr));
}
__device__ __forceinline__ void mma16816h(float d[4], const uint32_t a[4], uint32_t b0, uint32_t b1) {
    asm volatile("mma.sync.aligned.m16n8k16.row.col.f32.f16.f16.f32 "
        "{%0,%1,%2,%3}, {%4,%5,%6,%7}, {%8,%9}, {%0,%1,%2,%3};"
        : "+f"(d[0]), "+f"(d[1]), "+f"(d[2]), "+f"(d[3])
        : "r"(a[0]), "r"(a[1]), "r"(a[2]), "r"(a[3]), "r"(b0), "r"(b1));
}

#define NSTAGE 3

// ================ gemm1 mainloop: 1-term fp16, K-chunk 96, row stride 208 ================
// A 128 rows, B 160 rows. Warp grid 4m x 2n; warp tile 32 x 80.
#define G1_ROWB  208
#define G1_OFF_B (128*G1_ROWB)                     // 26624
#define G1_STAGE (G1_OFF_B + 160*G1_ROWB)          // 59904
#define SMEM1    (NSTAGE*G1_STAGE)                 // 179712

__device__ __forceinline__ void mma_mainloop_g1(float (&acc)[2][10][4],
    const HF* __restrict__ Ah, const HF* __restrict__ Bh,
    long m0, long n0, uint32_t smem_base)
{
    const int tid = threadIdx.x, lane = tid & 31, wid = tid >> 5;
    const int wm = wid & 3, wn = wid >> 2;
    const long rowb = (long)KPAD1 * 2;
    const int nch = KPAD1 / 96;                    // 126

    const char* bA = (const char*)(Ah + m0 * (long)KPAD1);
    const char* bB = (const char*)(Bh + n0 * (long)KPAD1);

    auto issue = [&](int c) {
        uint32_t st = smem_base + (c % NSTAGE) * G1_STAGE;
        long go = (long)c * 192;
        #pragma unroll
        for (int i = 0; i < 6; i++) {              // A: 1536 16B units (12 per row)
            int idx = tid + i * 256;
            int r = idx / 12, cc = (idx % 12) * 16;
            CP16(st + r * G1_ROWB + cc, bA + r * rowb + cc + go);
        }
        #pragma unroll
        for (int i = 0; i < 8; i++) {              // B: 1920 16B units
            int idx = tid + i * 256;
            if (idx < 1920) {
                int r = idx / 12, cc = (idx % 12) * 16;
                CP16(st + G1_OFF_B + r * G1_ROWB + cc, bB + r * rowb + cc + go);
            }
        }
        CP_COMMIT();
    };

    issue(0);
    issue(1);

    for (int c = 0; c < nch; c++) {
        if (c + 1 < nch) CP_WAIT1(); else CP_WAIT0();
        __syncthreads();

        uint32_t sA = smem_base + (c % NSTAGE) * G1_STAGE;
        #pragma unroll
        for (int s = 0; s < 6; s++) {
            uint32_t ah[2][4];
            #pragma unroll
            for (int t = 0; t < 2; t++) {
                uint32_t row = wm * 32 + t * 16 + (lane & 15);
                ldsm4(ah[t], sA + row * G1_ROWB + s * 32 + ((lane >> 4) & 1) * 16);
            }
            #pragma unroll
            for (int p = 0; p < 5; p++) {
                uint32_t bh[4];
                uint32_t row = wn * 80 + p * 16 + (lane & 7) + ((lane & 16) ? 8 : 0);
                ldsm4(bh, sA + G1_OFF_B + row * G1_ROWB + s * 32 + ((lane & 8) ? 16 : 0));
                #pragma unroll
                for (int t = 0; t < 2; t++)
                    #pragma unroll
                    for (int hh = 0; hh < 2; hh++)
                        mma16816h(acc[t][p * 2 + hh], ah[t], bh[hh * 2], bh[hh * 2 + 1]);
            }
        }
        if (c + 2 < nch) issue(c + 2);
    }
}

// ================ generic 1-term mainloop (gemm2 / sim), K-chunk 32, stride 80 ================
template<int BR>
__device__ __forceinline__ void mma_mainloop2(float (&accM)[2][BR/16][4],
    const HF* __restrict__ Ah, const HF* __restrict__ Bh,
    long m0, long n0, int kpad, int nch, uint32_t smem_base)
{
    constexpr int OFF_B  = 10240;            // A hi = 128*80
    constexpr int STAGE  = 10240 + BR * 80;
    constexpr int NP = BR / 32;

    const int tid = threadIdx.x, lane = tid & 31, wid = tid >> 5;
    const int wm = wid & 3, wn = wid >> 2;
    const long rowb = (long)kpad * 2;

    const char* bA  = (const char*)(Ah + m0 * (long)kpad);
    const char* bBh = (const char*)(Bh + n0 * (long)kpad);

    const int rA = tid >> 2, ccA = (tid & 3) * 16;

    auto issue = [&](int c) {
        uint32_t st = smem_base + (c % NSTAGE) * STAGE;
        long go = (long)c * 64;
        CP16(st + rA * 80 + ccA,        bA + rA * rowb + ccA + go);
        CP16(st + (rA + 64) * 80 + ccA, bA + (rA + 64) * rowb + ccA + go);
        #pragma unroll
        for (int i = 0; i < (BR * 4 + 255) / 256; i++) {
            int idx = tid + i * 256;
            if ((BR * 4) % 256 == 0 || idx < BR * 4) {
                int r = idx >> 2, cc = (idx & 3) * 16;
                CP16(st + OFF_B + r * 80 + cc, bBh + r * rowb + cc + go);
            }
        }
        CP_COMMIT();
    };

    issue(0);
    if (nch > 1) issue(1);

    for (int c = 0; c < nch; c++) {
        if (c + 1 < nch) CP_WAIT1(); else CP_WAIT0();
        __syncthreads();

        uint32_t sA = smem_base + (c % NSTAGE) * STAGE;
        #pragma unroll
        for (int s = 0; s < 2; s++) {
            uint32_t ah[2][4];
            #pragma unroll
            for (int t = 0; t < 2; t++) {
                uint32_t row = wm * 32 + t * 16 + (lane & 15);
                ldsm4(ah[t], sA + row * 80 + s * 32 + ((lane >> 4) & 1) * 16);
            }
            #pragma unroll
            for (int p = 0; p < NP; p++) {
                uint32_t bh[4];
                uint32_t row = wn * (BR / 2) + p * 16 + (lane & 7) + ((lane & 16) ? 8 : 0);
                uint32_t ad = sA + OFF_B + row * 80 + s * 32 + ((lane & 8) ? 16 : 0);
                ldsm4(bh, ad);
                #pragma unroll
                for (int t = 0; t < 2; t++)
                    #pragma unroll
                    for (int hh = 0; hh < 2; hh++) {
                        int j = p * 2 + hh;
                        mma16816h(accM[t][j], ah[t], bh[hh * 2], bh[hh * 2 + 1]);
                    }
            }
        }
        if (c + 2 < nch) issue(c + 2);
    }
}

#define SMEM2 (NSTAGE*(10240 + 128*80))      // gemm2 (1-term, BR=128): 61440
#define SMEMS (NSTAGE*(10240 + 256*80))      // sim   (1-term, BR=256): 92160

// ---------------- GEMM1: h = tanh(x @ W1 + b1), 1-term fp16, N-tile 160 ----------------
__global__ void __launch_bounds__(256) gemm1_mma(const HF* __restrict__ Ah,
                                                 const HF* __restrict__ Bh,
                                                 const float* __restrict__ bias,
                                                 HF* __restrict__ Hh)
{
    extern __shared__ char smem[];
    float acc[2][10][4];
    #pragma unroll
    for (int t = 0; t < 2; t++)
        #pragma unroll
        for (int j = 0; j < 10; j++)
            #pragma unroll
            for (int v = 0; v < 4; v++) acc[t][j][v] = 0.f;

    long m0 = (long)blockIdx.y * 128, n0 = (long)blockIdx.x * 160;
    mma_mainloop_g1(acc, Ah, Bh, m0, n0, smem_u32(smem));

    const int tid = threadIdx.x, lane = tid & 31, wid = tid >> 5;
    const int wm = wid & 3, wn = wid >> 2;
    const int rr = lane >> 2, q = lane & 3;
    #pragma unroll
    for (int t = 0; t < 2; t++) {
        long m = m0 + wm * 32 + t * 16 + rr;
        #pragma unroll
        for (int j = 0; j < 10; j++) {
            int n = (int)n0 + wn * 80 + j * 8 + 2 * q;   // even
            if (n < HPADK) {
                float a0 = (n     < Hn) ? tanhf(acc[t][j][0] + bias[n])     : 0.f;
                float a1 = (n + 1 < Hn) ? tanhf(acc[t][j][1] + bias[n + 1]) : 0.f;
                float b0 = (n     < Hn) ? tanhf(acc[t][j][2] + bias[n])     : 0.f;
                float b1 = (n + 1 < Hn) ? tanhf(acc[t][j][3] + bias[n + 1]) : 0.f;
                __half2 ha; ha.x = __float2half(a0); ha.y = __float2half(a1);
                __half2 hb; hb.x = __float2half(b0); hb.y = __float2half(b1);
                *(__half2*)(Hh + m * HPADK + n)       = ha;
                *(__half2*)(Hh + (m + 8) * HPADK + n) = hb;
            }
        }
    }
}

// ---------------- GEMM2: enc = h @ W2 + b2 (fp32 out), 1-term ----------------
__global__ void __launch_bounds__(256) gemm2_mma(const HF* __restrict__ Ah,
                                                 const HF* __restrict__ Bh,
                                                 const float* __restrict__ bias, float* __restrict__ E)
{
    extern __shared__ char smem[];
    float accM[2][8][4];
    #pragma unroll
    for (int t = 0; t < 2; t++)
        #pragma unroll
        for (int j = 0; j < 8; j++)
            #pragma unroll
            for (int v = 0; v < 4; v++) accM[t][j][v] = 0.f;

    long m0 = (long)blockIdx.y * 128, n0 = (long)blockIdx.x * 128;
    mma_mainloop2<128>(accM, Ah, Bh, m0, n0, HPADK, HPADK / 32, smem_u32(smem));

    const int tid = threadIdx.x, lane = tid & 31, wid = tid >> 5;
    const int wm = wid & 3, wn = wid >> 2;
    const int rr = lane >> 2, q = lane & 3;
    #pragma unroll
    for (int t = 0; t < 2; t++) {
        long m = m0 + wm * 32 + t * 16 + rr;
        #pragma unroll
        for (int j = 0; j < 8; j++) {
            int n = (int)n0 + wn * 64 + j * 8 + 2 * q;   // even
            if (n < ENCn) {
                float2 va, vb;
                va.x = accM[t][j][0] + bias[n];
                va.y = accM[t][j][1] + bias[n + 1];
                vb.x = accM[t][j][2] + bias[n];
                vb.y = accM[t][j][3] + bias[n + 1];
                *(float2*)(E + m * ENCn + n)       = va;
                *(float2*)(E + (m + 8) * ENCn + n) = vb;
            }
        }
    }
}

// ---------------- sim: new_output = log(mean_k exp(zn @ itn^T / tau) + 1) ----------------
// 1-term fp16, N-tile 256 (BR=256). Block (0,0) also finalizes kl.
__global__ void __launch_bounds__(256) sim_mma(const HF* __restrict__ Ah,
                                               const HF* __restrict__ Bh,
                                               float* __restrict__ no_out,
                                               const double* __restrict__ klp, float* __restrict__ kl_out)
{
    extern __shared__ char smem[];
    if (blockIdx.x == 0 && blockIdx.y == 0) {
        __shared__ double red[8];
        int tid = threadIdx.x;
        double s = klp[tid] + klp[tid + 256];
        #pragma unroll
        for (int o = 16; o; o >>= 1) s += __shfl_xor_sync(0xffffffffu, s, o);
        if ((tid & 31) == 0) red[tid >> 5] = s;
        __syncthreads();
        if (tid < 8) {
            double t = red[tid];
            #pragma unroll
            for (int o = 4; o; o >>= 1) t += __shfl_xor_sync(0xffu, t, o);
            if (tid == 0) *kl_out = (float)(0.5 * t / (double)ROWS);
        }
        __syncthreads();
    }

    float accM[2][16][4];
    #pragma unroll
    for (int t = 0; t < 2; t++)
        #pragma unroll
        for (int j = 0; j < 16; j++)
            #pragma unroll
            for (int v = 0; v < 4; v++) accM[t][j][v] = 0.f;

    long m0 = (long)blockIdx.y * 128, n0 = (long)blockIdx.x * 256;
    mma_mainloop2<256>(accM, Ah, Bh, m0, n0, KPAD2, KPAD2 / 32, smem_u32(smem));

    const int tid = threadIdx.x, lane = tid & 31, wid = tid >> 5;
    const int wm = wid & 3, wn = wid >> 2;
    const int q = lane & 3;
    long b = blockIdx.y * 4 + wm;     // user; warp's 32 m-rows = this user's 32 K rows
    #pragma unroll
    for (int j = 0; j < 16; j++) {
        float s0 = __expf(10.0f * accM[0][j][0]) + __expf(10.0f * accM[0][j][2])
                 + __expf(10.0f * accM[1][j][0]) + __expf(10.0f * accM[1][j][2]);
        float s1 = __expf(10.0f * accM[0][j][1]) + __expf(10.0f * accM[0][j][3])
                 + __expf(10.0f * accM[1][j][1]) + __expf(10.0f * accM[1][j][3]);
        #pragma unroll
        for (int off = 4; off < 32; off <<= 1) {
            s0 += __shfl_xor_sync(0xffffffffu, s0, off);
            s1 += __shfl_xor_sync(0xffffffffu, s1, off);
        }
        if (lane < 4) {
            int n = (int)n0 + wn * 128 + j * 8 + 2 * q;   // even
            if (n + 1 < In) {
                float2 v;
                v.x = logf(s0 * (1.0f / 32.0f) + 1.0f);
                v.y = logf(s1 * (1.0f / 32.0f) + 1.0f);
                *(float2*)(no_out + b * In + n) = v;
            } else if (n < In) {
                no_out[b * In + n] = logf(s0 * (1.0f / 32.0f) + 1.0f);
            }
        }
    }
}

// ---------------- fused prep: x | convW1(hi) | convW2(hi) | items_norm ----------------
#define X_BLKS  ROWS                       // 4096
#define W1_KT   (KPAD1/32)                 // 378
#define W1_BLKS (W1_KT*(NPAD1/32))         // 7560
#define W2_KT   (HPADK/32)                 // 19
#define W2_BLKS (W2_KT*(NPADW/32))         // 304
#define IT_BLKS (NPAD2/16)                 // 752
#define PREP_GRID (X_BLKS + W1_BLKS + W2_BLKS + IT_BLKS)

__global__ void __launch_bounds__(512) prep_kernel(
    const float* __restrict__ rating, const int* __restrict__ items_idx,
    const float* __restrict__ gram,   const float* __restrict__ W1,
    const float* __restrict__ W2,     const float* __restrict__ items,
    float* __restrict__ x_out, HF* __restrict__ xh,
    HF* __restrict__ w1h, HF* __restrict__ w2h,
    HF* __restrict__ ith)
{
    __shared__ float sbuf[12032];
    const int tid = threadIdx.x;
    int blk = blockIdx.x;

    if (blk < X_BLKS) {
        // ---- x = masked gram row / l2norm ----
        int bk = blk, b = bk >> 5;
        int row = items_idx[bk];
        const float4* r4 = (const float4*)(rating + (long)b * In);
        const float4* g4 = (const float4*)(gram + (long)row * In);
        float ss = 0.f;
        for (int i = tid; i < In / 4; i += 512) {
            float4 rv = r4[i];
            float4 gv = __ldcs(&g4[i]);          // gram row read once: streaming
            float4 m;
            m.x = (rv.x > 0.f) ? gv.x : 0.f;
            m.y = (rv.y > 0.f) ? gv.y : 0.f;
            m.z = (rv.z > 0.f) ? gv.z : 0.f;
            m.w = (rv.w > 0.f) ? gv.w : 0.f;
            ss += m.x * m.x + m.y * m.y + m.z * m.z + m.w * m.w;
            *(float4*)&sbuf[i * 4] = m;
        }
        __shared__ float red[16];
        #pragma unroll
        for (int o = 16; o; o >>= 1) ss += __shfl_xor_sync(0xffffffffu, ss, o);
        if ((tid & 31) == 0) red[tid >> 5] = ss;
        __syncthreads();
        if (tid < 16) {
            float t = red[tid];
            #pragma unroll
            for (int o = 8; o; o >>= 1) t += __shfl_xor_sync(0xffffu, t, o);
            if (tid == 0) red[0] = t;
        }
        __syncthreads();
        float inv = 1.0f / fmaxf(sqrtf(red[0]), 1e-12f);
        float* dst = x_out + (long)bk * In;   // 4B-aligned only
        for (int i = tid; i < In; i += 512) __stcs(dst + i, sbuf[i] * inv);
        uint32_t* dh = (uint32_t*)(xh + (size_t)bk * KPAD1);
        for (int i = tid; i < KPAD1 / 2; i += 512) {
            int i0 = 2 * i;
            float v0 = (i0     < In) ? sbuf[i0]     * inv : 0.f;
            float v1 = (i0 + 1 < In) ? sbuf[i0 + 1] * inv : 0.f;
            __half2 hp;
            hp.x = __float2half(v0);
            hp.y = __float2half(v1);
            dh[i] = *(uint32_t*)&hp;
        }
    } else if (blk < X_BLKS + W1_BLKS) {
        // ---- W1 [In,Hn] -> W1^T hi fp16 [NPAD1][KPAD1] ----
        int i = blk - X_BLKS;
        int kb = (i % W1_KT) * 32, nb = (i / W1_KT) * 32;
        int tx = tid & 31, ty = tid >> 5;    // 16 rows
        float (*t)[33] = (float(*)[33])sbuf;
        for (int j = ty; j < 32; j += 16) {
            int k = kb + j, n = nb + tx;
            t[j][tx] = (k < In && n < Hn) ? W1[(long)k * Hn + n] : 0.f;
        }
        __syncthreads();
        for (int j = ty; j < 32; j += 16) {
            int n = nb + j, k = kb + tx;
            w1h[(size_t)n * KPAD1 + k] = __float2half(t[tx][j]);
        }
    } else if (blk < X_BLKS + W1_BLKS + W2_BLKS) {
        // ---- W2 [Hn,ENCn] -> W2^T hi fp16 [NPADW][HPADK] ----
        int i = blk - X_BLKS - W1_BLKS;
        int kb = (i % W2_KT) * 32, nb = (i / W2_KT) * 32;
        int tx = tid & 31, ty = tid >> 5;
        float (*t)[33] = (float(*)[33])sbuf;
        for (int j = ty; j < 32; j += 16) {
            int k = kb + j, n = nb + tx;
            t[j][tx] = (k < Hn && n < ENCn) ? W2[(long)k * ENCn + n] : 0.f;
        }
        __syncthreads();
        for (int j = ty; j < 32; j += 16) {
            int n = nb + j, k = kb + tx;
            w2h[(size_t)n * HPADK + k] = __float2half(t[tx][j]);
        }
    } else {
        // ---- items l2-normalize -> fp16 hi, [NPAD2][KPAD2] ----
        int i = blk - X_BLKS - W1_BLKS - W2_BLKS;
        int warp = i * 16 + (tid >> 5);
        int lane = tid & 31;
        if (warp >= NPAD2) return;
        HF* dh = ith + (size_t)warp * KPAD2;
        if (warp >= In) {
            for (int j = lane; j < KPAD2; j += 32) dh[j] = __float2half(0.f);
            return;
        }
        const float* src = items + (long)warp * LATn;
        float v[7];
        float ss = 0.f;
        int cnt = 0;
        for (int j = lane; j < LATn; j += 32) { float t = src[j]; v[cnt++] = t; ss += t * t; }
        #pragma unroll
        for (int o = 16; o; o >>= 1) ss += __shfl_xor_sync(0xffffffffu, ss, o);
        float inv = 1.0f / fmaxf(sqrtf(ss), 1e-12f);
        cnt = 0;
        for (int j = lane; j < KPAD2; j += 32) {
            float t = (j < LATn) ? v[cnt++] * inv : 0.f;
            dh[j] = __float2half(t);
        }
    }
}

// ---------------- enc postprocess: z, zn-hi(fp16), kl partial per block ----------------
__global__ void postenc_kernel(const float* __restrict__ enc, float* __restrict__ z_out,
                               HF* __restrict__ znh, double* __restrict__ klp)
{
    __shared__ float kred[8];
    int wib  = threadIdx.x >> 5;                      // warp in block (8)
    int warp = blockIdx.x * 8 + wib;                  // global row
    int lane = threadIdx.x & 31;
    const float* e = enc + (long)warp * ENCn;
    float mv[7];
    float ss = 0.f, kl = 0.f;
    int cnt = 0;
    for (int j = lane; j < LATn; j += 32) {
        float m  = e[j];
        float lv = e[j + LATn];
        mv[cnt++] = m;
        ss += m * m;
        kl += m * m + (expm1f(lv) - lv);
    }
    #pragma unroll
    for (int o = 16; o; o >>= 1) {
        ss += __shfl_xor_sync(0xffffffffu, ss, o);
        kl += __shfl_xor_sync(0xffffffffu, kl, o);
    }
    float inv = 1.0f / fmaxf(sqrtf(ss), 1e-12f);
    cnt = 0;
    for (int j = lane; j < KPAD2; j += 32) {
        float t = 0.f;
        if (j < LATn) {
            z_out[(long)warp * LATn + j] = mv[cnt];
            t = mv[cnt++] * inv;
        }
        znh[(size_t)warp * KPAD2 + j] = __float2half(t);
    }
    if (lane == 0) kred[wib] = kl;
    __syncthreads();
    if (threadIdx.x < 8) {
        float t = kred[threadIdx.x];
        #pragma unroll
        for (int o = 4; o; o >>= 1) t += __shfl_xor_sync(0xffu, t, o);
        if (threadIdx.x == 0) klp[blockIdx.x] = (double)t;
    }
}

// ---------------- launch ----------------
extern "C" void kernel_launch(void* const* d_in, const int* in_sizes, int n_in,
                              void* d_out, int out_size)
{
    const float* rating    = (const float*)d_in[0];
    const int*   items_idx = (const int*)  d_in[1];
    const float* gram      = (const float*)d_in[2];
    const float* W1        = (const float*)d_in[3];
    const float* b1        = (const float*)d_in[4];
    const float* W2        = (const float*)d_in[5];
    const float* b2        = (const float*)d_in[6];
    const float* items     = (const float*)d_in[7];

    float* out    = (float*)d_out;
    float* z_out  = out + Z_OFF;
    float* no_out = out + NO_OFF;
    float* kl_out = out + KL_OFF;
    float* x_out  = out + X_OFF;

    float* enc; double* klp;
    HF *xh, *w1h, *hh, *w2h, *znh, *ith;
    cudaGetSymbolAddress((void**)&enc, g_enc);
    cudaGetSymbolAddress((void**)&klp, g_klp);
    cudaGetSymbolAddress((void**)&xh,  g_xh);
    cudaGetSymbolAddress((void**)&w1h, g_w1h);
    cudaGetSymbolAddress((void**)&hh,  g_hh);
    cudaGetSymbolAddress((void**)&w2h, g_w2h);
    cudaGetSymbolAddress((void**)&znh, g_znh);
    cudaGetSymbolAddress((void**)&ith, g_ith);

    cudaFuncSetAttribute(gemm1_mma, cudaFuncAttributeMaxDynamicSharedMemorySize, SMEM1);
    cudaFuncSetAttribute(gemm2_mma, cudaFuncAttributeMaxDynamicSharedMemorySize, SMEM2);
    cudaFuncSetAttribute(sim_mma,   cudaFuncAttributeMaxDynamicSharedMemorySize, SMEMS);

    // fused prep: x + W1^T(hi) + W2^T(hi) + items norm
    prep_kernel<<<PREP_GRID, 512>>>(rating, items_idx, gram, W1, W2, items,
                                    x_out, xh, w1h, w2h, ith);
    // h = tanh(x @ W1 + b1): 1-term fp16 HMMA, K-chunk 96, N-tile 160 (128 CTAs, single wave)
    gemm1_mma<<<dim3(NPAD1 / 160, ROWS / 128), 256, SMEM1>>>(xh, w1h, b1, hh);
    // enc = h @ W2 + b2: 1-term (128 CTAs)
    gemm2_mma<<<dim3(NPADW / 128, ROWS / 128), 256, SMEM2>>>(hh, w2h, b2, enc);
    postenc_kernel<<<ROWS / 8, 256>>>(enc, z_out, znh, klp);
    // new_output: 1-term fp16 HMMA, N-tile 256, fused exp/mean/log (+ kl finalize in block 0)
    sim_mma<<<dim3(NPAD2 / 256, ROWS / 128), 256, SMEMS>>>(znh, ith, no_out, klp, kl_out);
}

// round 15
// speedup vs baseline: 1.0480x; 1.0480x over previous
#include <cuda_runtime.h>
#include <cuda_fp16.h>
#include <math.h>
#include <stdint.h>

#define Bn   128
#define Kn   32
#define In   12000
#define Hn   600
#define LATn 200
#define ROWS (Bn*Kn)      // 4096
#define ENCn (2*LATn)     // 400

#define KPAD1 12032       // In padded to 64 (188 x 64-chunks)
#define NPAD1 640         // Hn padded to 160
#define KPAD2 224         // LATn padded (7 x 32-chunks)
#define NPAD2 12032       // In padded (47 x 256 n-tiles)
#define HPADK 608         // Hn padded to 32  (K of gemm2)
#define NPADW 512         // ENCn padded to 128 (N of gemm2)

#define Z_OFF  0
#define NO_OFF (ROWS*LATn)                 // 819200
#define KL_OFF (NO_OFF + Bn*In)            // 2355200
#define X_OFF  (KL_OFF + 1)                // 2355201

typedef __half HF;

// ---------------- scratch (no allocation allowed) ----------------
__device__ float  g_enc[ROWS*ENCn];
__device__ double g_klp[512];
__device__ HF g_xh [(size_t)ROWS*KPAD1];
__device__ HF g_w1h[(size_t)NPAD1*KPAD1];
__device__ HF g_hh [(size_t)ROWS*HPADK];
__device__ HF g_w2h[(size_t)NPADW*HPADK];
__device__ HF g_znh[(size_t)ROWS*KPAD2];
__device__ HF g_ith[(size_t)NPAD2*KPAD2];

// ==================== helpers ====================
__device__ __forceinline__ uint32_t smem_u32(const void* p) {
    uint32_t a;
    asm("{ .reg .u64 t; cvta.to.shared.u64 t, %1; cvt.u32.u64 %0, t; }" : "=r"(a) : "l"(p));
    return a;
}
#define CP16(dst, src) asm volatile("cp.async.cg.shared.global [%0], [%1], 16;" :: "r"(dst), "l"(src) : "memory")
#define CP_COMMIT()    asm volatile("cp.async.commit_group;" ::: "memory")
#define CP_WAIT1()     asm volatile("cp.async.wait_group 1;" ::: "memory")
#define CP_WAIT0()     asm volatile("cp.async.wait_group 0;" ::: "memory")

__device__ __forceinline__ void ldsm4(uint32_t r[4], uint32_t addr) {
    asm volatile("ldmatrix.sync.aligned.m8n8.x4.shared.b16 {%0,%1,%2,%3}, [%4];"
        : "=r"(r[0]), "=r"(r[1]), "=r"(r[2]), "=r"(r[3]) : "r"(addr));
}
__device__ __forceinline__ void mma16816h(float d[4], const uint32_t a[4], uint32_t b0, uint32_t b1) {
    asm volatile("mma.sync.aligned.m16n8k16.row.col.f32.f16.f16.f32 "
        "{%0,%1,%2,%3}, {%4,%5,%6,%7}, {%8,%9}, {%0,%1,%2,%3};"
        : "+f"(d[0]), "+f"(d[1]), "+f"(d[2]), "+f"(d[3])
        : "r"(a[0]), "r"(a[1]), "r"(a[2]), "r"(a[3]), "r"(b0), "r"(b1));
}

#define NSTAGE 3

// ================ gemm1 mainloop: 1-term fp16, K-chunk 64, row stride 144 ================
// A 128 rows, B 160 rows. Warp grid 4m x 2n; warp tile 32 x 80.
#define G1_ROWB  144
#define G1_OFF_B (128*G1_ROWB)                     // 18432
#define G1_STAGE (G1_OFF_B + 160*G1_ROWB)          // 41472
#define SMEM1    (NSTAGE*G1_STAGE)                 // 124416

__device__ __forceinline__ void mma_mainloop_g1(float (&acc)[2][10][4],
    const HF* __restrict__ Ah, const HF* __restrict__ Bh,
    long m0, long n0, uint32_t smem_base)
{
    const int tid = threadIdx.x, lane = tid & 31, wid = tid >> 5;
    const int wm = wid & 3, wn = wid >> 2;
    const long rowb = (long)KPAD1 * 2;
    const int nch = KPAD1 / 64;                    // 188

    const char* bA = (const char*)(Ah + m0 * (long)KPAD1);
    const char* bB = (const char*)(Bh + n0 * (long)KPAD1);

    auto issue = [&](int c) {
        uint32_t st = smem_base + (c % NSTAGE) * G1_STAGE;
        long go = (long)c * 128;
        #pragma unroll
        for (int i = 0; i < 4; i++) {              // A: 1024 16B units
            int idx = tid + i * 256;
            int r = idx >> 3, cc = (idx & 7) * 16;
            CP16(st + r * G1_ROWB + cc, bA + r * rowb + cc + go);
        }
        #pragma unroll
        for (int i = 0; i < 5; i++) {              // B: 1280 16B units
            int idx = tid + i * 256;
            int r = idx >> 3, cc = (idx & 7) * 16;
            CP16(st + G1_OFF_B + r * G1_ROWB + cc, bB + r * rowb + cc + go);
        }
        CP_COMMIT();
    };

    issue(0);
    issue(1);

    for (int c = 0; c < nch; c++) {
        if (c + 1 < nch) CP_WAIT1(); else CP_WAIT0();
        __syncthreads();

        uint32_t sA = smem_base + (c % NSTAGE) * G1_STAGE;
        #pragma unroll
        for (int s = 0; s < 4; s++) {
            uint32_t ah[2][4];
            #pragma unroll
            for (int t = 0; t < 2; t++) {
                uint32_t row = wm * 32 + t * 16 + (lane & 15);
                ldsm4(ah[t], sA + row * G1_ROWB + s * 32 + ((lane >> 4) & 1) * 16);
            }
            #pragma unroll
            for (int p = 0; p < 5; p++) {
                uint32_t bh[4];
                uint32_t row = wn * 80 + p * 16 + (lane & 7) + ((lane & 16) ? 8 : 0);
                ldsm4(bh, sA + G1_OFF_B + row * G1_ROWB + s * 32 + ((lane & 8) ? 16 : 0));
                #pragma unroll
                for (int t = 0; t < 2; t++)
                    #pragma unroll
                    for (int hh = 0; hh < 2; hh++)
                        mma16816h(acc[t][p * 2 + hh], ah[t], bh[hh * 2], bh[hh * 2 + 1]);
            }
        }
        if (c + 2 < nch) issue(c + 2);
    }
}

// ================ generic 1-term mainloop (gemm2 / sim), K-chunk 32, stride 80 ================
template<int BR>
__device__ __forceinline__ void mma_mainloop2(float (&accM)[2][BR/16][4],
    const HF* __restrict__ Ah, const HF* __restrict__ Bh,
    long m0, long n0, int kpad, int nch, uint32_t smem_base)
{
    constexpr int OFF_B  = 10240;            // A hi = 128*80
    constexpr int STAGE  = 10240 + BR * 80;
    constexpr int NP = BR / 32;

    const int tid = threadIdx.x, lane = tid & 31, wid = tid >> 5;
    const int wm = wid & 3, wn = wid >> 2;
    const long rowb = (long)kpad * 2;

    const char* bA  = (const char*)(Ah + m0 * (long)kpad);
    const char* bBh = (const char*)(Bh + n0 * (long)kpad);

    const int rA = tid >> 2, ccA = (tid & 3) * 16;

    auto issue = [&](int c) {
        uint32_t st = smem_base + (c % NSTAGE) * STAGE;
        long go = (long)c * 64;
        CP16(st + rA * 80 + ccA,        bA + rA * rowb + ccA + go);
        CP16(st + (rA + 64) * 80 + ccA, bA + (rA + 64) * rowb + ccA + go);
        #pragma unroll
        for (int i = 0; i < (BR * 4 + 255) / 256; i++) {
            int idx = tid + i * 256;
            if ((BR * 4) % 256 == 0 || idx < BR * 4) {
                int r = idx >> 2, cc = (idx & 3) * 16;
                CP16(st + OFF_B + r * 80 + cc, bBh + r * rowb + cc + go);
            }
        }
        CP_COMMIT();
    };

    issue(0);
    if (nch > 1) issue(1);

    for (int c = 0; c < nch; c++) {
        if (c + 1 < nch) CP_WAIT1(); else CP_WAIT0();
        __syncthreads();

        uint32_t sA = smem_base + (c % NSTAGE) * STAGE;
        #pragma unroll
        for (int s = 0; s < 2; s++) {
            uint32_t ah[2][4];
            #pragma unroll
            for (int t = 0; t < 2; t++) {
                uint32_t row = wm * 32 + t * 16 + (lane & 15);
                ldsm4(ah[t], sA + row * 80 + s * 32 + ((lane >> 4) & 1) * 16);
            }
            #pragma unroll
            for (int p = 0; p < NP; p++) {
                uint32_t bh[4];
                uint32_t row = wn * (BR / 2) + p * 16 + (lane & 7) + ((lane & 16) ? 8 : 0);
                uint32_t ad = sA + OFF_B + row * 80 + s * 32 + ((lane & 8) ? 16 : 0);
                ldsm4(bh, ad);
                #pragma unroll
                for (int t = 0; t < 2; t++)
                    #pragma unroll
                    for (int hh = 0; hh < 2; hh++) {
                        int j = p * 2 + hh;
                        mma16816h(accM[t][j], ah[t], bh[hh * 2], bh[hh * 2 + 1]);
                    }
            }
        }
        if (c + 2 < nch) issue(c + 2);
    }
}

#define SMEM2 (NSTAGE*(10240 + 128*80))      // gemm2 (1-term, BR=128): 61440
#define SMEMS (NSTAGE*(10240 + 256*80))      // sim   (1-term, BR=256): 92160

// ---------------- GEMM1: h = tanh(x @ W1 + b1), 1-term fp16, N-tile 160 ----------------
__global__ void __launch_bounds__(256) gemm1_mma(const HF* __restrict__ Ah,
                                                 const HF* __restrict__ Bh,
                                                 const float* __restrict__ bias,
                                                 HF* __restrict__ Hh)
{
    extern __shared__ char smem[];
    float acc[2][10][4];
    #pragma unroll
    for (int t = 0; t < 2; t++)
        #pragma unroll
        for (int j = 0; j < 10; j++)
            #pragma unroll
            for (int v = 0; v < 4; v++) acc[t][j][v] = 0.f;

    long m0 = (long)blockIdx.y * 128, n0 = (long)blockIdx.x * 160;
    mma_mainloop_g1(acc, Ah, Bh, m0, n0, smem_u32(smem));

    const int tid = threadIdx.x, lane = tid & 31, wid = tid >> 5;
    const int wm = wid & 3, wn = wid >> 2;
    const int rr = lane >> 2, q = lane & 3;
    #pragma unroll
    for (int t = 0; t < 2; t++) {
        long m = m0 + wm * 32 + t * 16 + rr;
        #pragma unroll
        for (int j = 0; j < 10; j++) {
            int n = (int)n0 + wn * 80 + j * 8 + 2 * q;   // even
            if (n < HPADK) {
                float a0 = (n     < Hn) ? tanhf(acc[t][j][0] + bias[n])     : 0.f;
                float a1 = (n + 1 < Hn) ? tanhf(acc[t][j][1] + bias[n + 1]) : 0.f;
                float b0 = (n     < Hn) ? tanhf(acc[t][j][2] + bias[n])     : 0.f;
                float b1 = (n + 1 < Hn) ? tanhf(acc[t][j][3] + bias[n + 1]) : 0.f;
                __half2 ha; ha.x = __float2half(a0); ha.y = __float2half(a1);
                __half2 hb; hb.x = __float2half(b0); hb.y = __float2half(b1);
                *(__half2*)(Hh + m * HPADK + n)       = ha;
                *(__half2*)(Hh + (m + 8) * HPADK + n) = hb;
            }
        }
    }
}

// ---------------- GEMM2: enc = h @ W2 + b2 (fp32 out), 1-term ----------------
__global__ void __launch_bounds__(256) gemm2_mma(const HF* __restrict__ Ah,
                                                 const HF* __restrict__ Bh,
                                                 const float* __restrict__ bias, float* __restrict__ E)
{
    extern __shared__ char smem[];
    float accM[2][8][4];
    #pragma unroll
    for (int t = 0; t < 2; t++)
        #pragma unroll
        for (int j = 0; j < 8; j++)
            #pragma unroll
            for (int v = 0; v < 4; v++) accM[t][j][v] = 0.f;

    long m0 = (long)blockIdx.y * 128, n0 = (long)blockIdx.x * 128;
    mma_mainloop2<128>(accM, Ah, Bh, m0, n0, HPADK, HPADK / 32, smem_u32(smem));

    const int tid = threadIdx.x, lane = tid & 31, wid = tid >> 5;
    const int wm = wid & 3, wn = wid >> 2;
    const int rr = lane >> 2, q = lane & 3;
    #pragma unroll
    for (int t = 0; t < 2; t++) {
        long m = m0 + wm * 32 + t * 16 + rr;
        #pragma unroll
        for (int j = 0; j < 8; j++) {
            int n = (int)n0 + wn * 64 + j * 8 + 2 * q;   // even
            if (n < ENCn) {
                float2 va, vb;
                va.x = accM[t][j][0] + bias[n];
                va.y = accM[t][j][1] + bias[n + 1];
                vb.x = accM[t][j][2] + bias[n];
                vb.y = accM[t][j][3] + bias[n + 1];
                *(float2*)(E + m * ENCn + n)       = va;
                *(float2*)(E + (m + 8) * ENCn + n) = vb;
            }
        }
    }
}

// ---------------- sim: new_output = log(mean_k exp(zn @ itn^T / tau) + 1) ----------------
// 1-term fp16, N-tile 256 (BR=256). Block (0,0) also finalizes kl.
__global__ void __launch_bounds__(256) sim_mma(const HF* __restrict__ Ah,
                                               const HF* __restrict__ Bh,
                                               float* __restrict__ no_out,
                                               const double* __restrict__ klp, float* __restrict__ kl_out)
{
    extern __shared__ char smem[];
    if (blockIdx.x == 0 && blockIdx.y == 0) {
        __shared__ double red[8];
        int tid = threadIdx.x;
        double s = klp[tid] + klp[tid + 256];
        #pragma unroll
        for (int o = 16; o; o >>= 1) s += __shfl_xor_sync(0xffffffffu, s, o);
        if ((tid & 31) == 0) red[tid >> 5] = s;
        __syncthreads();
        if (tid < 8) {
            double t = red[tid];
            #pragma unroll
            for (int o = 4; o; o >>= 1) t += __shfl_xor_sync(0xffu, t, o);
            if (tid == 0) *kl_out = (float)(0.5 * t / (double)ROWS);
        }
        __syncthreads();
    }

    float accM[2][16][4];
    #pragma unroll
    for (int t = 0; t < 2; t++)
        #pragma unroll
        for (int j = 0; j < 16; j++)
            #pragma unroll
            for (int v = 0; v < 4; v++) accM[t][j][v] = 0.f;

    long m0 = (long)blockIdx.y * 128, n0 = (long)blockIdx.x * 256;
    mma_mainloop2<256>(accM, Ah, Bh, m0, n0, KPAD2, KPAD2 / 32, smem_u32(smem));

    const int tid = threadIdx.x, lane = tid & 31, wid = tid >> 5;
    const int wm = wid & 3, wn = wid >> 2;
    const int q = lane & 3;
    long b = blockIdx.y * 4 + wm;     // user; warp's 32 m-rows = this user's 32 K rows
    #pragma unroll
    for (int j = 0; j < 16; j++) {
        float s0 = __expf(10.0f * accM[0][j][0]) + __expf(10.0f * accM[0][j][2])
                 + __expf(10.0f * accM[1][j][0]) + __expf(10.0f * accM[1][j][2]);
        float s1 = __expf(10.0f * accM[0][j][1]) + __expf(10.0f * accM[0][j][3])
                 + __expf(10.0f * accM[1][j][1]) + __expf(10.0f * accM[1][j][3]);
        #pragma unroll
        for (int off = 4; off < 32; off <<= 1) {
            s0 += __shfl_xor_sync(0xffffffffu, s0, off);
            s1 += __shfl_xor_sync(0xffffffffu, s1, off);
        }
        if (lane < 4) {
            int n = (int)n0 + wn * 128 + j * 8 + 2 * q;   // even
            if (n + 1 < In) {
                float2 v;
                v.x = logf(s0 * (1.0f / 32.0f) + 1.0f);
                v.y = logf(s1 * (1.0f / 32.0f) + 1.0f);
                *(float2*)(no_out + b * In + n) = v;
            } else if (n < In) {
                no_out[b * In + n] = logf(s0 * (1.0f / 32.0f) + 1.0f);
            }
        }
    }
}

// ---------------- fused prep: x | convW1(hi) | convW2(hi) | items_norm ----------------
#define X_BLKS  ROWS                       // 4096
#define W1_KT   (KPAD1/32)                 // 376
#define W1_BLKS (W1_KT*(NPAD1/32))         // 7520
#define W2_KT   (HPADK/32)                 // 19
#define W2_BLKS (W2_KT*(NPADW/32))         // 304
#define IT_BLKS (NPAD2/16)                 // 752
#define PREP_GRID (X_BLKS + W1_BLKS + W2_BLKS + IT_BLKS)

__global__ void __launch_bounds__(512) prep_kernel(
    const float* __restrict__ rating, const int* __restrict__ items_idx,
    const float* __restrict__ gram,   const float* __restrict__ W1,
    const float* __restrict__ W2,     const float* __restrict__ items,
    float* __restrict__ x_out, HF* __restrict__ xh,
    HF* __restrict__ w1h, HF* __restrict__ w2h,
    HF* __restrict__ ith)
{
    __shared__ float sbuf[12032];
    const int tid = threadIdx.x;
    int blk = blockIdx.x;

    if (blk < X_BLKS) {
        // ---- x = masked gram row / l2norm ----
        int bk = blk, b = bk >> 5;
        int row = items_idx[bk];
        const float4* r4 = (const float4*)(rating + (long)b * In);
        const float4* g4 = (const float4*)(gram + (long)row * In);
        float ss = 0.f;
        for (int i = tid; i < In / 4; i += 512) {
            float4 rv = r4[i];
            float4 gv = g4[i];
            float4 m;
            m.x = (rv.x > 0.f) ? gv.x : 0.f;
            m.y = (rv.y > 0.f) ? gv.y : 0.f;
            m.z = (rv.z > 0.f) ? gv.z : 0.f;
            m.w = (rv.w > 0.f) ? gv.w : 0.f;
            ss += m.x * m.x + m.y * m.y + m.z * m.z + m.w * m.w;
            *(float4*)&sbuf[i * 4] = m;
        }
        __shared__ float red[16];
        #pragma unroll
        for (int o = 16; o; o >>= 1) ss += __shfl_xor_sync(0xffffffffu, ss, o);
        if ((tid & 31) == 0) red[tid >> 5] = ss;
        __syncthreads();
        if (tid < 16) {
            float t = red[tid];
            #pragma unroll
            for (int o = 8; o; o >>= 1) t += __shfl_xor_sync(0xffffu, t, o);
            if (tid == 0) red[0] = t;
        }
        __syncthreads();
        float inv = 1.0f / fmaxf(sqrtf(red[0]), 1e-12f);
        float* dst = x_out + (long)bk * In;   // 4B-aligned only
        for (int i = tid; i < In; i += 512) dst[i] = sbuf[i] * inv;
        uint32_t* dh = (uint32_t*)(xh + (size_t)bk * KPAD1);
        for (int i = tid; i < KPAD1 / 2; i += 512) {
            int i0 = 2 * i;
            float v0 = (i0     < In) ? sbuf[i0]     * inv : 0.f;
            float v1 = (i0 + 1 < In) ? sbuf[i0 + 1] * inv : 0.f;
            __half2 hp;
            hp.x = __float2half(v0);
            hp.y = __float2half(v1);
            dh[i] = *(uint32_t*)&hp;
        }
    } else if (blk < X_BLKS + W1_BLKS) {
        // ---- W1 [In,Hn] -> W1^T hi fp16 [NPAD1][KPAD1] ----
        int i = blk - X_BLKS;
        int kb = (i % W1_KT) * 32, nb = (i / W1_KT) * 32;
        int tx = tid & 31, ty = tid >> 5;    // 16 rows
        float (*t)[33] = (float(*)[33])sbuf;
        for (int j = ty; j < 32; j += 16) {
            int k = kb + j, n = nb + tx;
            t[j][tx] = (k < In && n < Hn) ? W1[(long)k * Hn + n] : 0.f;
        }
        __syncthreads();
        for (int j = ty; j < 32; j += 16) {
            int n = nb + j, k = kb + tx;
            w1h[(size_t)n * KPAD1 + k] = __float2half(t[tx][j]);
        }
    } else if (blk < X_BLKS + W1_BLKS + W2_BLKS) {
        // ---- W2 [Hn,ENCn] -> W2^T hi fp16 [NPADW][HPADK] ----
        int i = blk - X_BLKS - W1_BLKS;
        int kb = (i % W2_KT) * 32, nb = (i / W2_KT) * 32;
        int tx = tid & 31, ty = tid >> 5;
        float (*t)[33] = (float(*)[33])sbuf;
        for (int j = ty; j < 32; j += 16) {
            int k = kb + j, n = nb + tx;
            t[j][tx] = (k < Hn && n < ENCn) ? W2[(long)k * ENCn + n] : 0.f;
        }
        __syncthreads();
        for (int j = ty; j < 32; j += 16) {
            int n = nb + j, k = kb + tx;
            w2h[(size_t)n * HPADK + k] = __float2half(t[tx][j]);
        }
    } else {
        // ---- items l2-normalize -> fp16 hi, [NPAD2][KPAD2] ----
        int i = blk - X_BLKS - W1_BLKS - W2_BLKS;
        int warp = i * 16 + (tid >> 5);
        int lane = tid & 31;
        if (warp >= NPAD2) return;
        HF* dh = ith + (size_t)warp * KPAD2;
        if (warp >= In) {
            for (int j = lane; j < KPAD2; j += 32) dh[j] = __float2half(0.f);
            return;
        }
        const float* src = items + (long)warp * LATn;
        float v[7];
        float ss = 0.f;
        int cnt = 0;
        for (int j = lane; j < LATn; j += 32) { float t = src[j]; v[cnt++] = t; ss += t * t; }
        #pragma unroll
        for (int o = 16; o; o >>= 1) ss += __shfl_xor_sync(0xffffffffu, ss, o);
        float inv = 1.0f / fmaxf(sqrtf(ss), 1e-12f);
        cnt = 0;
        for (int j = lane; j < KPAD2; j += 32) {
            float t = (j < LATn) ? v[cnt++] * inv : 0.f;
            dh[j] = __float2half(t);
        }
    }
}

// ---------------- enc postprocess: z, zn-hi(fp16), kl partial per block ----------------
__global__ void postenc_kernel(const float* __restrict__ enc, float* __restrict__ z_out,
                               HF* __restrict__ znh, double* __restrict__ klp)
{
    __shared__ float kred[8];
    int wib  = threadIdx.x >> 5;                      // warp in block (8)
    int warp = blockIdx.x * 8 + wib;                  // global row
    int lane = threadIdx.x & 31;
    const float* e = enc + (long)warp * ENCn;
    float mv[7];
    float ss = 0.f, kl = 0.f;
    int cnt = 0;
    for (int j = lane; j < LATn; j += 32) {
        float m  = e[j];
        float lv = e[j + LATn];
        mv[cnt++] = m;
        ss += m * m;
        kl += m * m + (expm1f(lv) - lv);
    }
    #pragma unroll
    for (int o = 16; o; o >>= 1) {
        ss += __shfl_xor_sync(0xffffffffu, ss, o);
        kl += __shfl_xor_sync(0xffffffffu, kl, o);
    }
    float inv = 1.0f / fmaxf(sqrtf(ss), 1e-12f);
    cnt = 0;
    for (int j = lane; j < KPAD2; j += 32) {
        float t = 0.f;
        if (j < LATn) {
            z_out[(long)warp * LATn + j] = mv[cnt];
            t = mv[cnt++] * inv;
        }
        znh[(size_t)warp * KPAD2 + j] = __float2half(t);
    }
    if (lane == 0) kred[wib] = kl;
    __syncthreads();
    if (threadIdx.x < 8) {
        float t = kred[threadIdx.x];
        #pragma unroll
        for (int o = 4; o; o >>= 1) t += __shfl_xor_sync(0xffu, t, o);
        if (threadIdx.x == 0) klp[blockIdx.x] = (double)t;
    }
}

// ---------------- launch ----------------
extern "C" void kernel_launch(void* const* d_in, const int* in_sizes, int n_in,
                              void* d_out, int out_size)
{
    const float* rating    = (const float*)d_in[0];
    const int*   items_idx = (const int*)  d_in[1];
    const float* gram      = (const float*)d_in[2];
    const float* W1        = (const float*)d_in[3];
    const float* b1        = (const float*)d_in[4];
    const float* W2        = (const float*)d_in[5];
    const float* b2        = (const float*)d_in[6];
    const float* items     = (const float*)d_in[7];

    float* out    = (float*)d_out;
    float* z_out  = out + Z_OFF;
    float* no_out = out + NO_OFF;
    float* kl_out = out + KL_OFF;
    float* x_out  = out + X_OFF;

    float* enc; double* klp;
    HF *xh, *w1h, *hh, *w2h, *znh, *ith;
    cudaGetSymbolAddress((void**)&enc, g_enc);
    cudaGetSymbolAddress((void**)&klp, g_klp);
    cudaGetSymbolAddress((void**)&xh,  g_xh);
    cudaGetSymbolAddress((void**)&w1h, g_w1h);
    cudaGetSymbolAddress((void**)&hh,  g_hh);
    cudaGetSymbolAddress((void**)&w2h, g_w2h);
    cudaGetSymbolAddress((void**)&znh, g_znh);
    cudaGetSymbolAddress((void**)&ith, g_ith);

    cudaFuncSetAttribute(gemm1_mma, cudaFuncAttributeMaxDynamicSharedMemorySize, SMEM1);
    cudaFuncSetAttribute(gemm2_mma, cudaFuncAttributeMaxDynamicSharedMemorySize, SMEM2);
    cudaFuncSetAttribute(sim_mma,   cudaFuncAttributeMaxDynamicSharedMemorySize, SMEMS);

    // fused prep: x + W1^T(hi) + W2^T(hi) + items norm
    prep_kernel<<<PREP_GRID, 512>>>(rating, items_idx, gram, W1, W2, items,
                                    x_out, xh, w1h, w2h, ith);
    // h = tanh(x @ W1 + b1): 1-term fp16 HMMA, K-chunk 64, N-tile 160 (128 CTAs, single wave)
    gemm1_mma<<<dim3(NPAD1 / 160, ROWS / 128), 256, SMEM1>>>(xh, w1h, b1, hh);
    // enc = h @ W2 + b2: 1-term (128 CTAs)
    gemm2_mma<<<dim3(NPADW / 128, ROWS / 128), 256, SMEM2>>>(hh, w2h, b2, enc);
    postenc_kernel<<<ROWS / 8, 256>>>(enc, z_out, znh, klp);
    // new_output: 1-term fp16 HMMA, N-tile 256, fused exp/mean/log (+ kl finalize in block 0)
    sim_mma<<<dim3(NPAD2 / 256, ROWS / 128), 256, SMEMS>>>(znh, ith, no_out, klp, kl_out);
}

// round 16
// speedup vs baseline: 1.0543x; 1.0061x over previous
#include <cuda_runtime.h>
#include <cuda_fp16.h>
#include <math.h>
#include <stdint.h>

#define Bn   128
#define Kn   32
#define In   12000
#define Hn   600
#define LATn 200
#define ROWS (Bn*Kn)      // 4096
#define ENCn (2*LATn)     // 400

#define KPAD1 12032       // In padded to 64 (188 x 64-chunks)
#define NPAD1 640         // Hn padded to 160
#define KPAD2 224         // LATn padded (7 x 32-chunks)
#define NPAD2 12032       // In padded (47 x 256 n-tiles)
#define HPADK 608         // Hn padded to 32  (K of gemm2)
#define NPADW 512         // ENCn padded to 128 (N of gemm2)

#define Z_OFF  0
#define NO_OFF (ROWS*LATn)                 // 819200
#define KL_OFF (NO_OFF + Bn*In)            // 2355200
#define X_OFF  (KL_OFF + 1)                // 2355201

typedef __half HF;

// ---------------- scratch (no allocation allowed) ----------------
__device__ float  g_enc[ROWS*ENCn];
__device__ double g_klp[128];
__device__ unsigned int g_ticket;
__device__ HF g_xh [(size_t)ROWS*KPAD1];
__device__ HF g_w1h[(size_t)NPAD1*KPAD1];
__device__ HF g_hh [(size_t)ROWS*HPADK];
__device__ HF g_w2h[(size_t)NPADW*HPADK];
__device__ HF g_znh[(size_t)ROWS*KPAD2];
__device__ HF g_ith[(size_t)NPAD2*KPAD2];

// ==================== helpers ====================
__device__ __forceinline__ uint32_t smem_u32(const void* p) {
    uint32_t a;
    asm("{ .reg .u64 t; cvta.to.shared.u64 t, %1; cvt.u32.u64 %0, t; }" : "=r"(a) : "l"(p));
    return a;
}
#define CP16(dst, src) asm volatile("cp.async.cg.shared.global [%0], [%1], 16;" :: "r"(dst), "l"(src) : "memory")
#define CP_COMMIT()    asm volatile("cp.async.commit_group;" ::: "memory")
#define CP_WAIT1()     asm volatile("cp.async.wait_group 1;" ::: "memory")
#define CP_WAIT0()     asm volatile("cp.async.wait_group 0;" ::: "memory")

__device__ __forceinline__ void ldsm4(uint32_t r[4], uint32_t addr) {
    asm volatile("ldmatrix.sync.aligned.m8n8.x4.shared.b16 {%0,%1,%2,%3}, [%4];"
        : "=r"(r[0]), "=r"(r[1]), "=r"(r[2]), "=r"(r[3]) : "r"(addr));
}
__device__ __forceinline__ void mma16816h(float d[4], const uint32_t a[4], uint32_t b0, uint32_t b1) {
    asm volatile("mma.sync.aligned.m16n8k16.row.col.f32.f16.f16.f32 "
        "{%0,%1,%2,%3}, {%4,%5,%6,%7}, {%8,%9}, {%0,%1,%2,%3};"
        : "+f"(d[0]), "+f"(d[1]), "+f"(d[2]), "+f"(d[3])
        : "r"(a[0]), "r"(a[1]), "r"(a[2]), "r"(a[3]), "r"(b0), "r"(b1));
}

#define NSTAGE 3

// ================ gemm1 mainloop: 1-term fp16, K-chunk 64, row stride 144 ================
// A 128 rows, B 160 rows. Warp grid 4m x 2n; warp tile 32 x 80.
#define G1_ROWB  144
#define G1_OFF_B (128*G1_ROWB)                     // 18432
#define G1_STAGE (G1_OFF_B + 160*G1_ROWB)          // 41472
#define SMEM1    (NSTAGE*G1_STAGE)                 // 124416

__device__ __forceinline__ void mma_mainloop_g1(float (&acc)[2][10][4],
    const HF* __restrict__ Ah, const HF* __restrict__ Bh,
    long m0, long n0, uint32_t smem_base)
{
    const int tid = threadIdx.x, lane = tid & 31, wid = tid >> 5;
    const int wm = wid & 3, wn = wid >> 2;
    const long rowb = (long)KPAD1 * 2;
    const int nch = KPAD1 / 64;                    // 188

    const char* bA = (const char*)(Ah + m0 * (long)KPAD1);
    const char* bB = (const char*)(Bh + n0 * (long)KPAD1);

    auto issue = [&](int c) {
        uint32_t st = smem_base + (c % NSTAGE) * G1_STAGE;
        long go = (long)c * 128;
        #pragma unroll
        for (int i = 0; i < 4; i++) {              // A: 1024 16B units
            int idx = tid + i * 256;
            int r = idx >> 3, cc = (idx & 7) * 16;
            CP16(st + r * G1_ROWB + cc, bA + r * rowb + cc + go);
        }
        #pragma unroll
        for (int i = 0; i < 5; i++) {              // B: 1280 16B units
            int idx = tid + i * 256;
            int r = idx >> 3, cc = (idx & 7) * 16;
            CP16(st + G1_OFF_B + r * G1_ROWB + cc, bB + r * rowb + cc + go);
        }
        CP_COMMIT();
    };

    issue(0);
    issue(1);

    for (int c = 0; c < nch; c++) {
        if (c + 1 < nch) CP_WAIT1(); else CP_WAIT0();
        __syncthreads();

        uint32_t sA = smem_base + (c % NSTAGE) * G1_STAGE;
        #pragma unroll
        for (int s = 0; s < 4; s++) {
            uint32_t ah[2][4];
            #pragma unroll
            for (int t = 0; t < 2; t++) {
                uint32_t row = wm * 32 + t * 16 + (lane & 15);
                ldsm4(ah[t], sA + row * G1_ROWB + s * 32 + ((lane >> 4) & 1) * 16);
            }
            #pragma unroll
            for (int p = 0; p < 5; p++) {
                uint32_t bh[4];
                uint32_t row = wn * 80 + p * 16 + (lane & 7) + ((lane & 16) ? 8 : 0);
                ldsm4(bh, sA + G1_OFF_B + row * G1_ROWB + s * 32 + ((lane & 8) ? 16 : 0));
                #pragma unroll
                for (int t = 0; t < 2; t++)
                    #pragma unroll
                    for (int hh = 0; hh < 2; hh++)
                        mma16816h(acc[t][p * 2 + hh], ah[t], bh[hh * 2], bh[hh * 2 + 1]);
            }
        }
        if (c + 2 < nch) issue(c + 2);
    }
}

// ================ generic 1-term mainloop (gemm2 / sim), K-chunk 32, stride 80 ================
template<int BR>
__device__ __forceinline__ void mma_mainloop2(float (&accM)[2][BR/16][4],
    const HF* __restrict__ Ah, const HF* __restrict__ Bh,
    long m0, long n0, int kpad, int nch, uint32_t smem_base)
{
    constexpr int OFF_B  = 10240;            // A hi = 128*80
    constexpr int STAGE  = 10240 + BR * 80;
    constexpr int NP = BR / 32;

    const int tid = threadIdx.x, lane = tid & 31, wid = tid >> 5;
    const int wm = wid & 3, wn = wid >> 2;
    const long rowb = (long)kpad * 2;

    const char* bA  = (const char*)(Ah + m0 * (long)kpad);
    const char* bBh = (const char*)(Bh + n0 * (long)kpad);

    const int rA = tid >> 2, ccA = (tid & 3) * 16;

    auto issue = [&](int c) {
        uint32_t st = smem_base + (c % NSTAGE) * STAGE;
        long go = (long)c * 64;
        CP16(st + rA * 80 + ccA,        bA + rA * rowb + ccA + go);
        CP16(st + (rA + 64) * 80 + ccA, bA + (rA + 64) * rowb + ccA + go);
        #pragma unroll
        for (int i = 0; i < (BR * 4 + 255) / 256; i++) {
            int idx = tid + i * 256;
            if ((BR * 4) % 256 == 0 || idx < BR * 4) {
                int r = idx >> 2, cc = (idx & 3) * 16;
                CP16(st + OFF_B + r * 80 + cc, bBh + r * rowb + cc + go);
            }
        }
        CP_COMMIT();
    };

    issue(0);
    if (nch > 1) issue(1);

    for (int c = 0; c < nch; c++) {
        if (c + 1 < nch) CP_WAIT1(); else CP_WAIT0();
        __syncthreads();

        uint32_t sA = smem_base + (c % NSTAGE) * STAGE;
        #pragma unroll
        for (int s = 0; s < 2; s++) {
            uint32_t ah[2][4];
            #pragma unroll
            for (int t = 0; t < 2; t++) {
                uint32_t row = wm * 32 + t * 16 + (lane & 15);
                ldsm4(ah[t], sA + row * 80 + s * 32 + ((lane >> 4) & 1) * 16);
            }
            #pragma unroll
            for (int p = 0; p < NP; p++) {
                uint32_t bh[4];
                uint32_t row = wn * (BR / 2) + p * 16 + (lane & 7) + ((lane & 16) ? 8 : 0);
                uint32_t ad = sA + OFF_B + row * 80 + s * 32 + ((lane & 8) ? 16 : 0);
                ldsm4(bh, ad);
                #pragma unroll
                for (int t = 0; t < 2; t++)
                    #pragma unroll
                    for (int hh = 0; hh < 2; hh++) {
                        int j = p * 2 + hh;
                        mma16816h(accM[t][j], ah[t], bh[hh * 2], bh[hh * 2 + 1]);
                    }
            }
        }
        if (c + 2 < nch) issue(c + 2);
    }
}

#define SMEM2 (NSTAGE*(10240 + 128*80))      // gemm2 (1-term, BR=128): 61440
#define SMEMS (NSTAGE*(10240 + 256*80))      // sim   (1-term, BR=256): 92160

// ---------------- GEMM1: h = tanh(x @ W1 + b1), 1-term fp16, N-tile 160 ----------------
__global__ void __launch_bounds__(256) gemm1_mma(const HF* __restrict__ Ah,
                                                 const HF* __restrict__ Bh,
                                                 const float* __restrict__ bias,
                                                 HF* __restrict__ Hh)
{
    extern __shared__ char smem[];
    float acc[2][10][4];
    #pragma unroll
    for (int t = 0; t < 2; t++)
        #pragma unroll
        for (int j = 0; j < 10; j++)
            #pragma unroll
            for (int v = 0; v < 4; v++) acc[t][j][v] = 0.f;

    long m0 = (long)blockIdx.y * 128, n0 = (long)blockIdx.x * 160;
    mma_mainloop_g1(acc, Ah, Bh, m0, n0, smem_u32(smem));

    const int tid = threadIdx.x, lane = tid & 31, wid = tid >> 5;
    const int wm = wid & 3, wn = wid >> 2;
    const int rr = lane >> 2, q = lane & 3;
    #pragma unroll
    for (int t = 0; t < 2; t++) {
        long m = m0 + wm * 32 + t * 16 + rr;
        #pragma unroll
        for (int j = 0; j < 10; j++) {
            int n = (int)n0 + wn * 80 + j * 8 + 2 * q;   // even
            if (n < HPADK) {
                float a0 = (n     < Hn) ? tanhf(acc[t][j][0] + bias[n])     : 0.f;
                float a1 = (n + 1 < Hn) ? tanhf(acc[t][j][1] + bias[n + 1]) : 0.f;
                float b0 = (n     < Hn) ? tanhf(acc[t][j][2] + bias[n])     : 0.f;
                float b1 = (n + 1 < Hn) ? tanhf(acc[t][j][3] + bias[n + 1]) : 0.f;
                __half2 ha; ha.x = __float2half(a0); ha.y = __float2half(a1);
                __half2 hb; hb.x = __float2half(b0); hb.y = __float2half(b1);
                *(__half2*)(Hh + m * HPADK + n)       = ha;
                *(__half2*)(Hh + (m + 8) * HPADK + n) = hb;
            }
        }
    }
}

// ---------------- GEMM2 + fused postenc ----------------
// Phase 1: enc = h @ W2 + b2 (fp32, global). Phase 2: device-wide ticket barrier
// (all 128 CTAs co-resident, single wave -> deadlock-free), then block bid
// post-processes rows bid*32..bid*32+31: z, zn-hi, kl partial.
__global__ void __launch_bounds__(256) gemm2_mma(const HF* __restrict__ Ah,
                                                 const HF* __restrict__ Bh,
                                                 const float* __restrict__ bias, float* __restrict__ E,
                                                 float* __restrict__ z_out, HF* __restrict__ znh,
                                                 double* __restrict__ klp)
{
    extern __shared__ char smem[];
    float accM[2][8][4];
    #pragma unroll
    for (int t = 0; t < 2; t++)
        #pragma unroll
        for (int j = 0; j < 8; j++)
            #pragma unroll
            for (int v = 0; v < 4; v++) accM[t][j][v] = 0.f;

    long m0 = (long)blockIdx.y * 128, n0 = (long)blockIdx.x * 128;
    mma_mainloop2<128>(accM, Ah, Bh, m0, n0, HPADK, HPADK / 32, smem_u32(smem));

    const int tid = threadIdx.x, lane = tid & 31, wid = tid >> 5;
    const int wm = wid & 3, wn = wid >> 2;
    const int rr = lane >> 2, q = lane & 3;
    #pragma unroll
    for (int t = 0; t < 2; t++) {
        long m = m0 + wm * 32 + t * 16 + rr;
        #pragma unroll
        for (int j = 0; j < 8; j++) {
            int n = (int)n0 + wn * 64 + j * 8 + 2 * q;   // even
            if (n < ENCn) {
                float2 va, vb;
                va.x = accM[t][j][0] + bias[n];
                va.y = accM[t][j][1] + bias[n + 1];
                vb.x = accM[t][j][2] + bias[n];
                vb.y = accM[t][j][3] + bias[n + 1];
                *(float2*)(E + m * ENCn + n)       = va;
                *(float2*)(E + (m + 8) * ENCn + n) = vb;
            }
        }
    }

    // ---- device-wide barrier (128 CTAs, all resident) ----
    __threadfence();
    __syncthreads();
    if (tid == 0) {
        atomicAdd(&g_ticket, 1u);
        while (atomicAdd(&g_ticket, 0u) < 128u) {}
    }
    __syncthreads();
    __threadfence();

    // ---- postenc: rows bid*32 .. +31, warp wib handles 4 rows ----
    __shared__ float kred[8];
    int bid  = blockIdx.x + blockIdx.y * 4;   // gridDim.x == 4
    int base = bid * 32;
    int wib  = wid;
    float kl = 0.f;
    #pragma unroll
    for (int rIt = 0; rIt < 4; rIt++) {
        int row = base + wib * 4 + rIt;
        const float* e = E + (long)row * ENCn;
        float mv[7];
        float ss = 0.f;
        int cnt = 0;
        for (int j = lane; j < LATn; j += 32) {
            float m  = e[j];
            float lv = e[j + LATn];
            mv[cnt++] = m;
            ss += m * m;
            kl += m * m + (expm1f(lv) - lv);
        }
        #pragma unroll
        for (int o = 16; o; o >>= 1) ss += __shfl_xor_sync(0xffffffffu, ss, o);
        float inv = 1.0f / fmaxf(sqrtf(ss), 1e-12f);
        cnt = 0;
        for (int j = lane; j < KPAD2; j += 32) {
            float t = 0.f;
            if (j < LATn) {
                z_out[(long)row * LATn + j] = mv[cnt];
                t = mv[cnt++] * inv;
            }
            znh[(size_t)row * KPAD2 + j] = __float2half(t);
        }
    }
    #pragma unroll
    for (int o = 16; o; o >>= 1) kl += __shfl_xor_sync(0xffffffffu, kl, o);
    if (lane == 0) kred[wib] = kl;
    __syncthreads();
    if (tid < 8) {
        float t = kred[tid];
        #pragma unroll
        for (int o = 4; o; o >>= 1) t += __shfl_xor_sync(0xffu, t, o);
        if (tid == 0) klp[bid] = (double)t;
    }
}

// ---------------- sim: new_output = log(mean_k exp(zn @ itn^T / tau) + 1) ----------------
// 1-term fp16, N-tile 256 (BR=256). Block (0,0) also finalizes kl (128 partials).
__global__ void __launch_bounds__(256) sim_mma(const HF* __restrict__ Ah,
                                               const HF* __restrict__ Bh,
                                               float* __restrict__ no_out,
                                               const double* __restrict__ klp, float* __restrict__ kl_out)
{
    extern __shared__ char smem[];
    if (blockIdx.x == 0 && blockIdx.y == 0) {
        __shared__ double red[8];
        int tid = threadIdx.x;
        double s = (tid < 128) ? klp[tid] : 0.0;
        #pragma unroll
        for (int o = 16; o; o >>= 1) s += __shfl_xor_sync(0xffffffffu, s, o);
        if ((tid & 31) == 0) red[tid >> 5] = s;
        __syncthreads();
        if (tid < 8) {
            double t = red[tid];
            #pragma unroll
            for (int o = 4; o; o >>= 1) t += __shfl_xor_sync(0xffu, t, o);
            if (tid == 0) *kl_out = (float)(0.5 * t / (double)ROWS);
        }
        __syncthreads();
    }

    float accM[2][16][4];
    #pragma unroll
    for (int t = 0; t < 2; t++)
        #pragma unroll
        for (int j = 0; j < 16; j++)
            #pragma unroll
            for (int v = 0; v < 4; v++) accM[t][j][v] = 0.f;

    long m0 = (long)blockIdx.y * 128, n0 = (long)blockIdx.x * 256;
    mma_mainloop2<256>(accM, Ah, Bh, m0, n0, KPAD2, KPAD2 / 32, smem_u32(smem));

    const int tid = threadIdx.x, lane = tid & 31, wid = tid >> 5;
    const int wm = wid & 3, wn = wid >> 2;
    const int q = lane & 3;
    long b = blockIdx.y * 4 + wm;     // user; warp's 32 m-rows = this user's 32 K rows
    #pragma unroll
    for (int j = 0; j < 16; j++) {
        float s0 = __expf(10.0f * accM[0][j][0]) + __expf(10.0f * accM[0][j][2])
                 + __expf(10.0f * accM[1][j][0]) + __expf(10.0f * accM[1][j][2]);
        float s1 = __expf(10.0f * accM[0][j][1]) + __expf(10.0f * accM[0][j][3])
                 + __expf(10.0f * accM[1][j][1]) + __expf(10.0f * accM[1][j][3]);
        #pragma unroll
        for (int off = 4; off < 32; off <<= 1) {
            s0 += __shfl_xor_sync(0xffffffffu, s0, off);
            s1 += __shfl_xor_sync(0xffffffffu, s1, off);
        }
        if (lane < 4) {
            int n = (int)n0 + wn * 128 + j * 8 + 2 * q;   // even
            if (n + 1 < In) {
                float2 v;
                v.x = __logf(s0 * (1.0f / 32.0f) + 1.0f);
                v.y = __logf(s1 * (1.0f / 32.0f) + 1.0f);
                *(float2*)(no_out + b * In + n) = v;
            } else if (n < In) {
                no_out[b * In + n] = __logf(s0 * (1.0f / 32.0f) + 1.0f);
            }
        }
    }
}

// ---------------- fused prep: x | convW1(hi) | convW2(hi) | items_norm ----------------
#define X_BLKS  ROWS                       // 4096
#define W1_KT   (KPAD1/32)                 // 376
#define W1_BLKS (W1_KT*(NPAD1/32))         // 7520
#define W2_KT   (HPADK/32)                 // 19
#define W2_BLKS (W2_KT*(NPADW/32))         // 304
#define IT_BLKS (NPAD2/16)                 // 752
#define PREP_GRID (X_BLKS + W1_BLKS + W2_BLKS + IT_BLKS)

__global__ void __launch_bounds__(512) prep_kernel(
    const float* __restrict__ rating, const int* __restrict__ items_idx,
    const float* __restrict__ gram,   const float* __restrict__ W1,
    const float* __restrict__ W2,     const float* __restrict__ items,
    float* __restrict__ x_out, HF* __restrict__ xh,
    HF* __restrict__ w1h, HF* __restrict__ w2h,
    HF* __restrict__ ith)
{
    __shared__ float sbuf[12032];
    const int tid = threadIdx.x;
    int blk = blockIdx.x;

    if (blk == 0 && tid == 0) g_ticket = 0;    // reset barrier for gemm2 (runs later in stream)

    if (blk < X_BLKS) {
        // ---- x = masked gram row / l2norm ----
        int bk = blk, b = bk >> 5;
        int row = items_idx[bk];
        const float4* r4 = (const float4*)(rating + (long)b * In);
        const float4* g4 = (const float4*)(gram + (long)row * In);
        float ss = 0.f;
        for (int i = tid; i < In / 4; i += 512) {
            float4 rv = r4[i];
            float4 gv = g4[i];
            float4 m;
            m.x = (rv.x > 0.f) ? gv.x : 0.f;
            m.y = (rv.y > 0.f) ? gv.y : 0.f;
            m.z = (rv.z > 0.f) ? gv.z : 0.f;
            m.w = (rv.w > 0.f) ? gv.w : 0.f;
            ss += m.x * m.x + m.y * m.y + m.z * m.z + m.w * m.w;
            *(float4*)&sbuf[i * 4] = m;
        }
        __shared__ float red[16];
        #pragma unroll
        for (int o = 16; o; o >>= 1) ss += __shfl_xor_sync(0xffffffffu, ss, o);
        if ((tid & 31) == 0) red[tid >> 5] = ss;
        __syncthreads();
        if (tid < 16) {
            float t = red[tid];
            #pragma unroll
            for (int o = 8; o; o >>= 1) t += __shfl_xor_sync(0xffffu, t, o);
            if (tid == 0) red[0] = t;
        }
        __syncthreads();
        float inv = 1.0f / fmaxf(sqrtf(red[0]), 1e-12f);
        float* dst = x_out + (long)bk * In;   // 4B-aligned only
        for (int i = tid; i < In; i += 512) __stcs(dst + i, sbuf[i] * inv);   // write-once: stream
        uint32_t* dh = (uint32_t*)(xh + (size_t)bk * KPAD1);
        for (int i = tid; i < KPAD1 / 2; i += 512) {
            int i0 = 2 * i;
            float v0 = (i0     < In) ? sbuf[i0]     * inv : 0.f;
            float v1 = (i0 + 1 < In) ? sbuf[i0 + 1] * inv : 0.f;
            __half2 hp;
            hp.x = __float2half(v0);
            hp.y = __float2half(v1);
            dh[i] = *(uint32_t*)&hp;
        }
    } else if (blk < X_BLKS + W1_BLKS) {
        // ---- W1 [In,Hn] -> W1^T hi fp16 [NPAD1][KPAD1] ----
        int i = blk - X_BLKS;
        int kb = (i % W1_KT) * 32, nb = (i / W1_KT) * 32;
        int tx = tid & 31, ty = tid >> 5;    // 16 rows
        float (*t)[33] = (float(*)[33])sbuf;
        for (int j = ty; j < 32; j += 16) {
            int k = kb + j, n = nb + tx;
            t[j][tx] = (k < In && n < Hn) ? W1[(long)k * Hn + n] : 0.f;
        }
        __syncthreads();
        for (int j = ty; j < 32; j += 16) {
            int n = nb + j, k = kb + tx;
            w1h[(size_t)n * KPAD1 + k] = __float2half(t[tx][j]);
        }
    } else if (blk < X_BLKS + W1_BLKS + W2_BLKS) {
        // ---- W2 [Hn,ENCn] -> W2^T hi fp16 [NPADW][HPADK] ----
        int i = blk - X_BLKS - W1_BLKS;
        int kb = (i % W2_KT) * 32, nb = (i / W2_KT) * 32;
        int tx = tid & 31, ty = tid >> 5;
        float (*t)[33] = (float(*)[33])sbuf;
        for (int j = ty; j < 32; j += 16) {
            int k = kb + j, n = nb + tx;
            t[j][tx] = (k < Hn && n < ENCn) ? W2[(long)k * ENCn + n] : 0.f;
        }
        __syncthreads();
        for (int j = ty; j < 32; j += 16) {
            int n = nb + j, k = kb + tx;
            w2h[(size_t)n * HPADK + k] = __float2half(t[tx][j]);
        }
    } else {
        // ---- items l2-normalize -> fp16 hi, [NPAD2][KPAD2] ----
        int i = blk - X_BLKS - W1_BLKS - W2_BLKS;
        int warp = i * 16 + (tid >> 5);
        int lane = tid & 31;
        if (warp >= NPAD2) return;
        HF* dh = ith + (size_t)warp * KPAD2;
        if (warp >= In) {
            for (int j = lane; j < KPAD2; j += 32) dh[j] = __float2half(0.f);
            return;
        }
        const float* src = items + (long)warp * LATn;
        float v[7];
        float ss = 0.f;
        int cnt = 0;
        for (int j = lane; j < LATn; j += 32) { float t = src[j]; v[cnt++] = t; ss += t * t; }
        #pragma unroll
        for (int o = 16; o; o >>= 1) ss += __shfl_xor_sync(0xffffffffu, ss, o);
        float inv = 1.0f / fmaxf(sqrtf(ss), 1e-12f);
        cnt = 0;
        for (int j = lane; j < KPAD2; j += 32) {
            float t = (j < LATn) ? v[cnt++] * inv : 0.f;
            dh[j] = __float2half(t);
        }
    }
}

// ---------------- launch ----------------
extern "C" void kernel_launch(void* const* d_in, const int* in_sizes, int n_in,
                              void* d_out, int out_size)
{
    const float* rating    = (const float*)d_in[0];
    const int*   items_idx = (const int*)  d_in[1];
    const float* gram      = (const float*)d_in[2];
    const float* W1        = (const float*)d_in[3];
    const float* b1        = (const float*)d_in[4];
    const float* W2        = (const float*)d_in[5];
    const float* b2        = (const float*)d_in[6];
    const float* items     = (const float*)d_in[7];

    float* out    = (float*)d_out;
    float* z_out  = out + Z_OFF;
    float* no_out = out + NO_OFF;
    float* kl_out = out + KL_OFF;
    float* x_out  = out + X_OFF;

    float* enc; double* klp;
    HF *xh, *w1h, *hh, *w2h, *znh, *ith;
    cudaGetSymbolAddress((void**)&enc, g_enc);
    cudaGetSymbolAddress((void**)&klp, g_klp);
    cudaGetSymbolAddress((void**)&xh,  g_xh);
    cudaGetSymbolAddress((void**)&w1h, g_w1h);
    cudaGetSymbolAddress((void**)&hh,  g_hh);
    cudaGetSymbolAddress((void**)&w2h, g_w2h);
    cudaGetSymbolAddress((void**)&znh, g_znh);
    cudaGetSymbolAddress((void**)&ith, g_ith);

    cudaFuncSetAttribute(gemm1_mma, cudaFuncAttributeMaxDynamicSharedMemorySize, SMEM1);
    cudaFuncSetAttribute(gemm2_mma, cudaFuncAttributeMaxDynamicSharedMemorySize, SMEM2);
    cudaFuncSetAttribute(sim_mma,   cudaFuncAttributeMaxDynamicSharedMemorySize, SMEMS);

    // fused prep: x + W1^T(hi) + W2^T(hi) + items norm (+ ticket reset)
    prep_kernel<<<PREP_GRID, 512>>>(rating, items_idx, gram, W1, W2, items,
                                    x_out, xh, w1h, w2h, ith);
    // h = tanh(x @ W1 + b1): 1-term fp16 HMMA, K-chunk 64, N-tile 160 (128 CTAs, single wave)
    gemm1_mma<<<dim3(NPAD1 / 160, ROWS / 128), 256, SMEM1>>>(xh, w1h, b1, hh);
    // enc = h @ W2 + b2 + fused postenc (barrier; 128 CTAs, single wave)
    gemm2_mma<<<dim3(NPADW / 128, ROWS / 128), 256, SMEM2>>>(hh, w2h, b2, enc, z_out, znh, klp);
    // new_output: 1-term fp16 HMMA, N-tile 256, fused exp/mean/log (+ kl finalize in block 0)
    sim_mma<<<dim3(NPAD2 / 256, ROWS / 128), 256, SMEMS>>>(znh, ith, no_out, klp, kl_out);
}

// round 17
// speedup vs baseline: 1.0586x; 1.0041x over previous
#include <cuda_runtime.h>
#include <cuda_fp16.h>
#include <math.h>
#include <stdint.h>

#define Bn   128
#define Kn   32
#define In   12000
#define Hn   600
#define LATn 200
#define ROWS (Bn*Kn)      // 4096
#define ENCn (2*LATn)     // 400

#define KPAD1 12032       // In padded to 64 (188 x 64-chunks)
#define NPAD1 640         // Hn padded to 160
#define KPAD2 224         // LATn padded (7 x 32-chunks)
#define NPAD2 12032       // In padded (47 x 256 n-tiles)
#define HPADK 608         // Hn padded to 32  (K of gemm2)
#define NPADW 512         // ENCn padded to 128 (N of gemm2)

#define Z_OFF  0
#define NO_OFF (ROWS*LATn)                 // 819200
#define KL_OFF (NO_OFF + Bn*In)            // 2355200
#define X_OFF  (KL_OFF + 1)                // 2355201

typedef __half HF;

// ---------------- scratch (no allocation allowed) ----------------
__device__ float  g_enc[ROWS*ENCn];
__device__ double g_klp[128];
__device__ unsigned int g_ticket;
__device__ HF g_xh [(size_t)ROWS*KPAD1];
__device__ HF g_w1h[(size_t)NPAD1*KPAD1];
__device__ HF g_hh [(size_t)ROWS*HPADK];
__device__ HF g_w2h[(size_t)NPADW*HPADK];
__device__ HF g_znh[(size_t)ROWS*KPAD2];
__device__ HF g_ith[(size_t)NPAD2*KPAD2];

// ==================== helpers ====================
__device__ __forceinline__ uint32_t smem_u32(const void* p) {
    uint32_t a;
    asm("{ .reg .u64 t; cvta.to.shared.u64 t, %1; cvt.u32.u64 %0, t; }" : "=r"(a) : "l"(p));
    return a;
}
#define CP16(dst, src) asm volatile("cp.async.cg.shared.global [%0], [%1], 16;" :: "r"(dst), "l"(src) : "memory")
#define CP_COMMIT()    asm volatile("cp.async.commit_group;" ::: "memory")
#define CP_WAIT1()     asm volatile("cp.async.wait_group 1;" ::: "memory")
#define CP_WAIT0()     asm volatile("cp.async.wait_group 0;" ::: "memory")

__device__ __forceinline__ void ldsm4(uint32_t r[4], uint32_t addr) {
    asm volatile("ldmatrix.sync.aligned.m8n8.x4.shared.b16 {%0,%1,%2,%3}, [%4];"
        : "=r"(r[0]), "=r"(r[1]), "=r"(r[2]), "=r"(r[3]) : "r"(addr));
}
__device__ __forceinline__ void mma16816h(float d[4], const uint32_t a[4], uint32_t b0, uint32_t b1) {
    asm volatile("mma.sync.aligned.m16n8k16.row.col.f32.f16.f16.f32 "
        "{%0,%1,%2,%3}, {%4,%5,%6,%7}, {%8,%9}, {%0,%1,%2,%3};"
        : "+f"(d[0]), "+f"(d[1]), "+f"(d[2]), "+f"(d[3])
        : "r"(a[0]), "r"(a[1]), "r"(a[2]), "r"(a[3]), "r"(b0), "r"(b1));
}

#define NSTAGE 3

// ================ gemm1 mainloop: 1-term fp16, K-chunk 64, row stride 144 ================
// A 128 rows, B 160 rows. Warp grid 4m x 2n; warp tile 32 x 80.
#define G1_ROWB  144
#define G1_OFF_B (128*G1_ROWB)                     // 18432
#define G1_STAGE (G1_OFF_B + 160*G1_ROWB)          // 41472
#define SMEM1    (NSTAGE*G1_STAGE)                 // 124416

__device__ __forceinline__ void mma_mainloop_g1(float (&acc)[2][10][4],
    const HF* __restrict__ Ah, const HF* __restrict__ Bh,
    long m0, long n0, uint32_t smem_base)
{
    const int tid = threadIdx.x, lane = tid & 31, wid = tid >> 5;
    const int wm = wid & 3, wn = wid >> 2;
    const long rowb = (long)KPAD1 * 2;
    const int nch = KPAD1 / 64;                    // 188

    const char* bA = (const char*)(Ah + m0 * (long)KPAD1);
    const char* bB = (const char*)(Bh + n0 * (long)KPAD1);

    auto issue = [&](int c) {
        uint32_t st = smem_base + (c % NSTAGE) * G1_STAGE;
        long go = (long)c * 128;
        #pragma unroll
        for (int i = 0; i < 4; i++) {              // A: 1024 16B units
            int idx = tid + i * 256;
            int r = idx >> 3, cc = (idx & 7) * 16;
            CP16(st + r * G1_ROWB + cc, bA + r * rowb + cc + go);
        }
        #pragma unroll
        for (int i = 0; i < 5; i++) {              // B: 1280 16B units
            int idx = tid + i * 256;
            int r = idx >> 3, cc = (idx & 7) * 16;
            CP16(st + G1_OFF_B + r * G1_ROWB + cc, bB + r * rowb + cc + go);
        }
        CP_COMMIT();
    };

    issue(0);
    issue(1);

    for (int c = 0; c < nch; c++) {
        if (c + 1 < nch) CP_WAIT1(); else CP_WAIT0();
        __syncthreads();

        uint32_t sA = smem_base + (c % NSTAGE) * G1_STAGE;
        #pragma unroll
        for (int s = 0; s < 4; s++) {
            uint32_t ah[2][4];
            #pragma unroll
            for (int t = 0; t < 2; t++) {
                uint32_t row = wm * 32 + t * 16 + (lane & 15);
                ldsm4(ah[t], sA + row * G1_ROWB + s * 32 + ((lane >> 4) & 1) * 16);
            }
            #pragma unroll
            for (int p = 0; p < 5; p++) {
                uint32_t bh[4];
                uint32_t row = wn * 80 + p * 16 + (lane & 7) + ((lane & 16) ? 8 : 0);
                ldsm4(bh, sA + G1_OFF_B + row * G1_ROWB + s * 32 + ((lane & 8) ? 16 : 0));
                #pragma unroll
                for (int t = 0; t < 2; t++)
                    #pragma unroll
                    for (int hh = 0; hh < 2; hh++)
                        mma16816h(acc[t][p * 2 + hh], ah[t], bh[hh * 2], bh[hh * 2 + 1]);
            }
        }
        if (c + 2 < nch) issue(c + 2);
    }
}

// ================ generic 1-term mainloop (gemm2 / sim), K-chunk 32, stride 80 ================
template<int BR>
__device__ __forceinline__ void mma_mainloop2(float (&accM)[2][BR/16][4],
    const HF* __restrict__ Ah, const HF* __restrict__ Bh,
    long m0, long n0, int kpad, int nch, uint32_t smem_base)
{
    constexpr int OFF_B  = 10240;            // A hi = 128*80
    constexpr int STAGE  = 10240 + BR * 80;
    constexpr int NP = BR / 32;

    const int tid = threadIdx.x, lane = tid & 31, wid = tid >> 5;
    const int wm = wid & 3, wn = wid >> 2;
    const long rowb = (long)kpad * 2;

    const char* bA  = (const char*)(Ah + m0 * (long)kpad);
    const char* bBh = (const char*)(Bh + n0 * (long)kpad);

    const int rA = tid >> 2, ccA = (tid & 3) * 16;

    auto issue = [&](int c) {
        uint32_t st = smem_base + (c % NSTAGE) * STAGE;
        long go = (long)c * 64;
        CP16(st + rA * 80 + ccA,        bA + rA * rowb + ccA + go);
        CP16(st + (rA + 64) * 80 + ccA, bA + (rA + 64) * rowb + ccA + go);
        #pragma unroll
        for (int i = 0; i < (BR * 4 + 255) / 256; i++) {
            int idx = tid + i * 256;
            if ((BR * 4) % 256 == 0 || idx < BR * 4) {
                int r = idx >> 2, cc = (idx & 3) * 16;
                CP16(st + OFF_B + r * 80 + cc, bBh + r * rowb + cc + go);
            }
        }
        CP_COMMIT();
    };

    issue(0);
    if (nch > 1) issue(1);

    for (int c = 0; c < nch; c++) {
        if (c + 1 < nch) CP_WAIT1(); else CP_WAIT0();
        __syncthreads();

        uint32_t sA = smem_base + (c % NSTAGE) * STAGE;
        #pragma unroll
        for (int s = 0; s < 2; s++) {
            uint32_t ah[2][4];
            #pragma unroll
            for (int t = 0; t < 2; t++) {
                uint32_t row = wm * 32 + t * 16 + (lane & 15);
                ldsm4(ah[t], sA + row * 80 + s * 32 + ((lane >> 4) & 1) * 16);
            }
            #pragma unroll
            for (int p = 0; p < NP; p++) {
                uint32_t bh[4];
                uint32_t row = wn * (BR / 2) + p * 16 + (lane & 7) + ((lane & 16) ? 8 : 0);
                uint32_t ad = sA + OFF_B + row * 80 + s * 32 + ((lane & 8) ? 16 : 0);
                ldsm4(bh, ad);
                #pragma unroll
                for (int t = 0; t < 2; t++)
                    #pragma unroll
                    for (int hh = 0; hh < 2; hh++) {
                        int j = p * 2 + hh;
                        mma16816h(accM[t][j], ah[t], bh[hh * 2], bh[hh * 2 + 1]);
                    }
            }
        }
        if (c + 2 < nch) issue(c + 2);
    }
}

#define SMEM2 (NSTAGE*(10240 + 128*80))      // gemm2 (1-term, BR=128): 61440
#define SMEMS (NSTAGE*(10240 + 256*80))      // sim   (1-term, BR=256): 92160

// ---------------- GEMM1: h = tanh(x @ W1 + b1), 1-term fp16, N-tile 160 ----------------
__global__ void __launch_bounds__(256) gemm1_mma(const HF* __restrict__ Ah,
                                                 const HF* __restrict__ Bh,
                                                 const float* __restrict__ bias,
                                                 HF* __restrict__ Hh)
{
    extern __shared__ char smem[];
    float acc[2][10][4];
    #pragma unroll
    for (int t = 0; t < 2; t++)
        #pragma unroll
        for (int j = 0; j < 10; j++)
            #pragma unroll
            for (int v = 0; v < 4; v++) acc[t][j][v] = 0.f;

    long m0 = (long)blockIdx.y * 128, n0 = (long)blockIdx.x * 160;
    mma_mainloop_g1(acc, Ah, Bh, m0, n0, smem_u32(smem));

    const int tid = threadIdx.x, lane = tid & 31, wid = tid >> 5;
    const int wm = wid & 3, wn = wid >> 2;
    const int rr = lane >> 2, q = lane & 3;
    #pragma unroll
    for (int t = 0; t < 2; t++) {
        long m = m0 + wm * 32 + t * 16 + rr;
        #pragma unroll
        for (int j = 0; j < 10; j++) {
            int n = (int)n0 + wn * 80 + j * 8 + 2 * q;   // even
            if (n < HPADK) {
                float a0 = (n     < Hn) ? tanhf(acc[t][j][0] + bias[n])     : 0.f;
                float a1 = (n + 1 < Hn) ? tanhf(acc[t][j][1] + bias[n + 1]) : 0.f;
                float b0 = (n     < Hn) ? tanhf(acc[t][j][2] + bias[n])     : 0.f;
                float b1 = (n + 1 < Hn) ? tanhf(acc[t][j][3] + bias[n + 1]) : 0.f;
                __half2 ha; ha.x = __float2half(a0); ha.y = __float2half(a1);
                __half2 hb; hb.x = __float2half(b0); hb.y = __float2half(b1);
                *(__half2*)(Hh + m * HPADK + n)       = ha;
                *(__half2*)(Hh + (m + 8) * HPADK + n) = hb;
            }
        }
    }
}

// ---------------- GEMM2 + fused postenc ----------------
// Phase 1: enc = h @ W2 + b2 (fp32, global). Phase 2: device-wide ticket barrier
// (all 128 CTAs co-resident, single wave -> deadlock-free), then block bid
// post-processes rows bid*32..bid*32+31: z, zn-hi, kl partial.
__global__ void __launch_bounds__(256) gemm2_mma(const HF* __restrict__ Ah,
                                                 const HF* __restrict__ Bh,
                                                 const float* __restrict__ bias, float* __restrict__ E,
                                                 float* __restrict__ z_out, HF* __restrict__ znh,
                                                 double* __restrict__ klp)
{
    extern __shared__ char smem[];
    float accM[2][8][4];
    #pragma unroll
    for (int t = 0; t < 2; t++)
        #pragma unroll
        for (int j = 0; j < 8; j++)
            #pragma unroll
            for (int v = 0; v < 4; v++) accM[t][j][v] = 0.f;

    long m0 = (long)blockIdx.y * 128, n0 = (long)blockIdx.x * 128;
    mma_mainloop2<128>(accM, Ah, Bh, m0, n0, HPADK, HPADK / 32, smem_u32(smem));

    const int tid = threadIdx.x, lane = tid & 31, wid = tid >> 5;
    const int wm = wid & 3, wn = wid >> 2;
    const int rr = lane >> 2, q = lane & 3;
    #pragma unroll
    for (int t = 0; t < 2; t++) {
        long m = m0 + wm * 32 + t * 16 + rr;
        #pragma unroll
        for (int j = 0; j < 8; j++) {
            int n = (int)n0 + wn * 64 + j * 8 + 2 * q;   // even
            if (n < ENCn) {
                float2 va, vb;
                va.x = accM[t][j][0] + bias[n];
                va.y = accM[t][j][1] + bias[n + 1];
                vb.x = accM[t][j][2] + bias[n];
                vb.y = accM[t][j][3] + bias[n + 1];
                *(float2*)(E + m * ENCn + n)       = va;
                *(float2*)(E + (m + 8) * ENCn + n) = vb;
            }
        }
    }

    // ---- device-wide barrier (128 CTAs, all resident) ----
    __threadfence();
    __syncthreads();
    if (tid == 0) {
        atomicAdd(&g_ticket, 1u);
        while (atomicAdd(&g_ticket, 0u) < 128u) {}
    }
    __syncthreads();
    __threadfence();

    // ---- postenc: rows bid*32 .. +31, warp wib handles 4 rows ----
    __shared__ float kred[8];
    int bid  = blockIdx.x + blockIdx.y * 4;   // gridDim.x == 4
    int base = bid * 32;
    int wib  = wid;
    float kl = 0.f;
    #pragma unroll
    for (int rIt = 0; rIt < 4; rIt++) {
        int row = base + wib * 4 + rIt;
        const float* e = E + (long)row * ENCn;
        float mv[7];
        float ss = 0.f;
        int cnt = 0;
        for (int j = lane; j < LATn; j += 32) {
            float m  = e[j];
            float lv = e[j + LATn];
            mv[cnt++] = m;
            ss += m * m;
            kl += m * m + (expm1f(lv) - lv);
        }
        #pragma unroll
        for (int o = 16; o; o >>= 1) ss += __shfl_xor_sync(0xffffffffu, ss, o);
        float inv = 1.0f / fmaxf(sqrtf(ss), 1e-12f);
        cnt = 0;
        for (int j = lane; j < KPAD2; j += 32) {
            float t = 0.f;
            if (j < LATn) {
                z_out[(long)row * LATn + j] = mv[cnt];
                t = mv[cnt++] * inv;
            }
            znh[(size_t)row * KPAD2 + j] = __float2half(t);
        }
    }
    #pragma unroll
    for (int o = 16; o; o >>= 1) kl += __shfl_xor_sync(0xffffffffu, kl, o);
    if (lane == 0) kred[wib] = kl;
    __syncthreads();
    if (tid < 8) {
        float t = kred[tid];
        #pragma unroll
        for (int o = 4; o; o >>= 1) t += __shfl_xor_sync(0xffu, t, o);
        if (tid == 0) klp[bid] = (double)t;
    }
}

// ---------------- sim: new_output = log(mean_k exp(zn @ itn^T / tau) + 1) ----------------
// 1-term fp16, N-tile 256 (BR=256). Block (0,0) also finalizes kl (128 partials).
__global__ void __launch_bounds__(256) sim_mma(const HF* __restrict__ Ah,
                                               const HF* __restrict__ Bh,
                                               float* __restrict__ no_out,
                                               const double* __restrict__ klp, float* __restrict__ kl_out)
{
    extern __shared__ char smem[];
    if (blockIdx.x == 0 && blockIdx.y == 0) {
        __shared__ double red[8];
        int tid = threadIdx.x;
        double s = (tid < 128) ? klp[tid] : 0.0;
        #pragma unroll
        for (int o = 16; o; o >>= 1) s += __shfl_xor_sync(0xffffffffu, s, o);
        if ((tid & 31) == 0) red[tid >> 5] = s;
        __syncthreads();
        if (tid < 8) {
            double t = red[tid];
            #pragma unroll
            for (int o = 4; o; o >>= 1) t += __shfl_xor_sync(0xffu, t, o);
            if (tid == 0) *kl_out = (float)(0.5 * t / (double)ROWS);
        }
        __syncthreads();
    }

    float accM[2][16][4];
    #pragma unroll
    for (int t = 0; t < 2; t++)
        #pragma unroll
        for (int j = 0; j < 16; j++)
            #pragma unroll
            for (int v = 0; v < 4; v++) accM[t][j][v] = 0.f;

    long m0 = (long)blockIdx.y * 128, n0 = (long)blockIdx.x * 256;
    mma_mainloop2<256>(accM, Ah, Bh, m0, n0, KPAD2, KPAD2 / 32, smem_u32(smem));

    const int tid = threadIdx.x, lane = tid & 31, wid = tid >> 5;
    const int wm = wid & 3, wn = wid >> 2;
    const int q = lane & 3;
    long b = blockIdx.y * 4 + wm;     // user; warp's 32 m-rows = this user's 32 K rows
    #pragma unroll
    for (int j = 0; j < 16; j++) {
        float s0 = __expf(10.0f * accM[0][j][0]) + __expf(10.0f * accM[0][j][2])
                 + __expf(10.0f * accM[1][j][0]) + __expf(10.0f * accM[1][j][2]);
        float s1 = __expf(10.0f * accM[0][j][1]) + __expf(10.0f * accM[0][j][3])
                 + __expf(10.0f * accM[1][j][1]) + __expf(10.0f * accM[1][j][3]);
        #pragma unroll
        for (int off = 4; off < 32; off <<= 1) {
            s0 += __shfl_xor_sync(0xffffffffu, s0, off);
            s1 += __shfl_xor_sync(0xffffffffu, s1, off);
        }
        if (lane < 4) {
            int n = (int)n0 + wn * 128 + j * 8 + 2 * q;   // even
            if (n + 1 < In) {
                float2 v;
                v.x = __logf(s0 * (1.0f / 32.0f) + 1.0f);
                v.y = __logf(s1 * (1.0f / 32.0f) + 1.0f);
                *(float2*)(no_out + b * In + n) = v;
            } else if (n < In) {
                no_out[b * In + n] = __logf(s0 * (1.0f / 32.0f) + 1.0f);
            }
        }
    }
}

// ---------------- fused prep: x | convW1(hi) | convW2(hi) | items_norm ----------------
#define X_BLKS  ROWS                       // 4096
#define W1_KT   (KPAD1/32)                 // 376
#define W1_BLKS (W1_KT*(NPAD1/32))         // 7520
#define W2_KT   (HPADK/32)                 // 19
#define W2_BLKS (W2_KT*(NPADW/32))         // 304
#define IT_BLKS (NPAD2/16)                 // 752
#define PREP_GRID (X_BLKS + W1_BLKS + W2_BLKS + IT_BLKS)

__global__ void __launch_bounds__(512) prep_kernel(
    const float* __restrict__ rating, const int* __restrict__ items_idx,
    const float* __restrict__ gram,   const float* __restrict__ W1,
    const float* __restrict__ W2,     const float* __restrict__ items,
    float* __restrict__ x_out, HF* __restrict__ xh,
    HF* __restrict__ w1h, HF* __restrict__ w2h,
    HF* __restrict__ ith)
{
    __shared__ float sbuf[12032];
    const int tid = threadIdx.x;
    int blk = blockIdx.x;

    if (blk == 0 && tid == 0) g_ticket = 0;    // reset barrier for gemm2 (runs later in stream)

    if (blk < X_BLKS) {
        // ---- x = masked gram row / l2norm ----
        int bk = blk, b = bk >> 5;
        int row = items_idx[bk];
        const float4* r4 = (const float4*)(rating + (long)b * In);
        const float4* g4 = (const float4*)(gram + (long)row * In);
        float ss = 0.f;
        for (int i = tid; i < In / 4; i += 512) {
            float4 rv = r4[i];
            float4 gv = g4[i];
            float4 m;
            m.x = (rv.x > 0.f) ? gv.x : 0.f;
            m.y = (rv.y > 0.f) ? gv.y : 0.f;
            m.z = (rv.z > 0.f) ? gv.z : 0.f;
            m.w = (rv.w > 0.f) ? gv.w : 0.f;
            ss += m.x * m.x + m.y * m.y + m.z * m.z + m.w * m.w;
            *(float4*)&sbuf[i * 4] = m;
        }
        __shared__ float red[16];
        #pragma unroll
        for (int o = 16; o; o >>= 1) ss += __shfl_xor_sync(0xffffffffu, ss, o);
        if ((tid & 31) == 0) red[tid >> 5] = ss;
        __syncthreads();
        if (tid < 16) {
            float t = red[tid];
            #pragma unroll
            for (int o = 8; o; o >>= 1) t += __shfl_xor_sync(0xffffu, t, o);
            if (tid == 0) red[0] = t;
        }
        __syncthreads();
        float inv = 1.0f / fmaxf(sqrtf(red[0]), 1e-12f);
        float* dst = x_out + (long)bk * In;   // 4B-aligned only
        for (int i = tid; i < In; i += 512) __stcs(dst + i, sbuf[i] * inv);   // write-once: stream
        uint32_t* dh = (uint32_t*)(xh + (size_t)bk * KPAD1);
        for (int i = tid; i < KPAD1 / 2; i += 512) {
            int i0 = 2 * i;
            float v0 = (i0     < In) ? sbuf[i0]     * inv : 0.f;
            float v1 = (i0 + 1 < In) ? sbuf[i0 + 1] * inv : 0.f;
            __half2 hp;
            hp.x = __float2half(v0);
            hp.y = __float2half(v1);
            dh[i] = *(uint32_t*)&hp;
        }
    } else if (blk < X_BLKS + W1_BLKS) {
        // ---- W1 [In,Hn] -> W1^T hi fp16 [NPAD1][KPAD1] ----
        int i = blk - X_BLKS;
        int kb = (i % W1_KT) * 32, nb = (i / W1_KT) * 32;
        int tx = tid & 31, ty = tid >> 5;    // 16 rows
        float (*t)[33] = (float(*)[33])sbuf;
        for (int j = ty; j < 32; j += 16) {
            int k = kb + j, n = nb + tx;
            t[j][tx] = (k < In && n < Hn) ? W1[(long)k * Hn + n] : 0.f;
        }
        __syncthreads();
        for (int j = ty; j < 32; j += 16) {
            int n = nb + j, k = kb + tx;
            w1h[(size_t)n * KPAD1 + k] = __float2half(t[tx][j]);
        }
    } else if (blk < X_BLKS + W1_BLKS + W2_BLKS) {
        // ---- W2 [Hn,ENCn] -> W2^T hi fp16 [NPADW][HPADK] ----
        int i = blk - X_BLKS - W1_BLKS;
        int kb = (i % W2_KT) * 32, nb = (i / W2_KT) * 32;
        int tx = tid & 31, ty = tid >> 5;
        float (*t)[33] = (float(*)[33])sbuf;
        for (int j = ty; j < 32; j += 16) {
            int k = kb + j, n = nb + tx;
            t[j][tx] = (k < Hn && n < ENCn) ? W2[(long)k * ENCn + n] : 0.f;
        }
        __syncthreads();
        for (int j = ty; j < 32; j += 16) {
            int n = nb + j, k = kb + tx;
            w2h[(size_t)n * HPADK + k] = __float2half(t[tx][j]);
        }
    } else {
        // ---- items l2-normalize -> fp16 hi, [NPAD2][KPAD2] ----
        int i = blk - X_BLKS - W1_BLKS - W2_BLKS;
        int warp = i * 16 + (tid >> 5);
        int lane = tid & 31;
        if (warp >= NPAD2) return;
        HF* dh = ith + (size_t)warp * KPAD2;
        if (warp >= In) {
            for (int j = lane; j < KPAD2; j += 32) dh[j] = __float2half(0.f);
            return;
        }
        const float* src = items + (long)warp * LATn;
        float v[7];
        float ss = 0.f;
        int cnt = 0;
        for (int j = lane; j < LATn; j += 32) { float t = src[j]; v[cnt++] = t; ss += t * t; }
        #pragma unroll
        for (int o = 16; o; o >>= 1) ss += __shfl_xor_sync(0xffffffffu, ss, o);
        float inv = 1.0f / fmaxf(sqrtf(ss), 1e-12f);
        cnt = 0;
        for (int j = lane; j < KPAD2; j += 32) {
            float t = (j < LATn) ? v[cnt++] * inv : 0.f;
            dh[j] = __float2half(t);
        }
    }
}

// ---------------- launch ----------------
extern "C" void kernel_launch(void* const* d_in, const int* in_sizes, int n_in,
                              void* d_out, int out_size)
{
    const float* rating    = (const float*)d_in[0];
    const int*   items_idx = (const int*)  d_in[1];
    const float* gram      = (const float*)d_in[2];
    const float* W1        = (const float*)d_in[3];
    const float* b1        = (const float*)d_in[4];
    const float* W2        = (const float*)d_in[5];
    const float* b2        = (const float*)d_in[6];
    const float* items     = (const float*)d_in[7];

    float* out    = (float*)d_out;
    float* z_out  = out + Z_OFF;
    float* no_out = out + NO_OFF;
    float* kl_out = out + KL_OFF;
    float* x_out  = out + X_OFF;

    float* enc; double* klp;
    HF *xh, *w1h, *hh, *w2h, *znh, *ith;
    cudaGetSymbolAddress((void**)&enc, g_enc);
    cudaGetSymbolAddress((void**)&klp, g_klp);
    cudaGetSymbolAddress((void**)&xh,  g_xh);
    cudaGetSymbolAddress((void**)&w1h, g_w1h);
    cudaGetSymbolAddress((void**)&hh,  g_hh);
    cudaGetSymbolAddress((void**)&w2h, g_w2h);
    cudaGetSymbolAddress((void**)&znh, g_znh);
    cudaGetSymbolAddress((void**)&ith, g_ith);

    cudaFuncSetAttribute(gemm1_mma, cudaFuncAttributeMaxDynamicSharedMemorySize, SMEM1);
    cudaFuncSetAttribute(gemm2_mma, cudaFuncAttributeMaxDynamicSharedMemorySize, SMEM2);
    cudaFuncSetAttribute(sim_mma,   cudaFuncAttributeMaxDynamicSharedMemorySize, SMEMS);

    // fused prep: x + W1^T(hi) + W2^T(hi) + items norm (+ ticket reset)
    prep_kernel<<<PREP_GRID, 512>>>(rating, items_idx, gram, W1, W2, items,
                                    x_out, xh, w1h, w2h, ith);
    // h = tanh(x @ W1 + b1): 1-term fp16 HMMA, K-chunk 64, N-tile 160 (128 CTAs, single wave)
    gemm1_mma<<<dim3(NPAD1 / 160, ROWS / 128), 256, SMEM1>>>(xh, w1h, b1, hh);
    // enc = h @ W2 + b2 + fused postenc (barrier; 128 CTAs, single wave)
    gemm2_mma<<<dim3(NPADW / 128, ROWS / 128), 256, SMEM2>>>(hh, w2h, b2, enc, z_out, znh, klp);
    // new_output: 1-term fp16 HMMA, N-tile 256, fused exp/mean/log (+ kl finalize in block 0)
    sim_mma<<<dim3(NPAD2 / 256, ROWS / 128), 256, SMEMS>>>(znh, ith, no_out, klp, kl_out);
}